// round 4
// baseline (speedup 1.0000x reference)
#include <cuda_runtime.h>
#include <math.h>
#include <stdint.h>

// ---------------- problem constants ----------------
constexpr int D      = 4096;
constexpr int NTOT   = 2000;
constexpr int NL     = 500;
constexpr int NU     = 1500;
constexpr int WAY    = 100;
constexpr int NUW    = NU * WAY;      // 150000
constexpr int WAYD   = WAY * D;       // 409600
constexpr int MAXIT  = 1000;
constexpr float LAMB   = 10.0f;
constexpr float ALPHAC = 0.2f;

// ---------------- device scratch ----------------
__device__ float g_X1[NTOT * D];
__device__ float g_Z[NTOT * D];
__device__ float g_zn2[NTOT];
__device__ float g_meanL[D], g_meanU[D];
__device__ float g_Sl[WAYD];
__device__ float g_mus[WAYD];
__device__ float g_mn2[WAY];
__device__ float g_Cpart[8 * NUW];
__device__ float g_Pu[NUW];
__device__ float g_Epart[4 * WAYD];
__device__ float g_KsumPart[16];
__device__ unsigned g_errGlob[2];
__device__ float g_colsumPart[2][15 * 128];
__device__ float g_colPpart[15 * 128];
__device__ int   g_barCount;
__device__ unsigned g_barGen;
__device__ int   g_accN;

// ---------------- helpers ----------------
__device__ __forceinline__ float blockReduceSum(float v) {
    static __shared__ float sh[32];
    __syncthreads();
    int lane = threadIdx.x & 31, wid = threadIdx.x >> 5;
    #pragma unroll
    for (int off = 16; off; off >>= 1) v += __shfl_xor_sync(0xffffffffu, v, off);
    if (lane == 0) sh[wid] = v;
    __syncthreads();
    int nw = (blockDim.x + 31) >> 5;
    float r = 0.0f;
    if (wid == 0) {
        r = (lane < nw) ? sh[lane] : 0.0f;
        #pragma unroll
        for (int off = 16; off; off >>= 1) r += __shfl_xor_sync(0xffffffffu, r, off);
        if (lane == 0) sh[0] = r;
    }
    __syncthreads();
    return sh[0];
}

__device__ __forceinline__ uint32_t f2tf32(float f) {
    uint32_t r;
    asm("cvt.rna.tf32.f32 %0, %1;" : "=r"(r) : "f"(f));
    return r;
}

__device__ __forceinline__ void mma_tf32(float c[4], uint32_t a0, uint32_t a1,
                                         uint32_t a2, uint32_t a3,
                                         uint32_t b0, uint32_t b1) {
    asm volatile(
        "mma.sync.aligned.m16n8k8.row.col.f32.tf32.tf32.f32 "
        "{%0,%1,%2,%3}, {%4,%5,%6,%7}, {%8,%9}, {%0,%1,%2,%3};\n"
        : "+f"(c[0]), "+f"(c[1]), "+f"(c[2]), "+f"(c[3])
        : "r"(a0), "r"(a1), "r"(a2), "r"(a3), "r"(b0), "r"(b1));
}

// ---------------- preprocessing ----------------
__global__ void k_pre1(const float* __restrict__ X) {
    int row = blockIdx.x, t = threadIdx.x;
    if (row == 0 && t == 0) g_accN = 0;
    __shared__ float buf[D];
    float ss = 0.0f;
    for (int d = t; d < D; d += blockDim.x) {
        float v = sqrtf(X[(size_t)row * D + d] + 1e-6f);
        buf[d] = v; ss += v * v;
    }
    ss = blockReduceSum(ss);
    float inv = 1.0f / fmaxf(sqrtf(ss), 1e-12f);
    for (int d = t; d < D; d += blockDim.x) g_X1[(size_t)row * D + d] = buf[d] * inv;
}

__global__ void k_colmeans() {
    int lane = threadIdx.x & 63;
    int part = threadIdx.x >> 6;         // 0..3
    int d = blockIdx.x * 64 + lane;
    __shared__ float sh[4][64];
    float sL = 0.0f;
    for (int i = part * 125; i < (part + 1) * 125; i++) sL += g_X1[(size_t)i * D + d];
    sh[part][lane] = sL;
    __syncthreads();
    if (part == 0)
        g_meanL[d] = (sh[0][lane] + sh[1][lane] + sh[2][lane] + sh[3][lane]) * (1.0f / NL);
    __syncthreads();
    float sU = 0.0f;
    for (int i = NL + part * 375; i < NL + (part + 1) * 375; i++) sU += g_X1[(size_t)i * D + d];
    sh[part][lane] = sU;
    __syncthreads();
    if (part == 0)
        g_meanU[d] = (sh[0][lane] + sh[1][lane] + sh[2][lane] + sh[3][lane]) * (1.0f / NU);
}

__global__ void k_pre2() {
    int row = blockIdx.x, t = threadIdx.x;
    __shared__ float buf[D];
    const float* mean = (row < NL) ? g_meanL : g_meanU;
    float ss = 0.0f;
    for (int d = t; d < D; d += blockDim.x) {
        float v = g_X1[(size_t)row * D + d] - mean[d];
        buf[d] = v; ss += v * v;
    }
    ss = blockReduceSum(ss);
    float inv = 1.0f / fmaxf(sqrtf(ss), 1e-12f);
    if (t == 0) g_zn2[row] = ss * inv * inv;
    for (int d = t; d < D; d += blockDim.x) g_Z[(size_t)row * D + d] = buf[d] * inv;
}

__global__ void k_Sl() {
    int idx = blockIdx.x * blockDim.x + threadIdx.x;
    if (idx >= WAYD) return;
    int c = idx >> 12, d = idx & (D - 1);
    float s = 0.0f;
    #pragma unroll
    for (int k = 0; k < 5; k++) s += g_Z[(size_t)(k * WAY + c) * D + d];
    g_Sl[idx] = s;
    g_mus[idx] = s * 0.2f;
}

// ===== tensor-core gram: Cpart[ks][i,j] = sum over 512-k-chunk Zu[i,k]*mus[j,k]
__global__ void __launch_bounds__(256) k_gram() {
    const int r0 = blockIdx.x * 64;
    const int k0 = blockIdx.y * 512;
    const int t  = threadIdx.x;
    const int w  = t >> 5, lane = t & 31;
    const int gid = lane >> 2, tig = lane & 3;
    const int mw = w >> 1;            // 0..3
    const int nw = w & 1;             // 0..1
    const int m0w = mw * 16;
    const int n0w = nw * 56;

    __shared__ uint32_t As[64][33];   // [m][k] tf32 bits
    __shared__ uint32_t Bs[112][33];  // [n][k]

    float c[7][4];
    #pragma unroll
    for (int i = 0; i < 7; i++)
        #pragma unroll
        for (int jj = 0; jj < 4; jj++) c[i][jj] = 0.0f;

    const float* Zu = g_Z + (size_t)NL * D;
    const int lr = t >> 3;            // 0..31
    const int lc = (t & 7) * 4;       // k group

    for (int kt = 0; kt < 512; kt += 32) {
        const int kbase = k0 + kt;
        #pragma unroll
        for (int p = 0; p < 2; p++) {
            int r = lr + 32 * p;
            float4 v = make_float4(0.f, 0.f, 0.f, 0.f);
            if (r0 + r < NU) v = *(const float4*)&Zu[(size_t)(r0 + r) * D + kbase + lc];
            As[r][lc + 0] = f2tf32(v.x); As[r][lc + 1] = f2tf32(v.y);
            As[r][lc + 2] = f2tf32(v.z); As[r][lc + 3] = f2tf32(v.w);
        }
        #pragma unroll
        for (int p = 0; p < 4; p++) {
            int r = lr + 32 * p;
            if (r < 112) {
                float4 v = make_float4(0.f, 0.f, 0.f, 0.f);
                if (r < WAY) v = *(const float4*)&g_mus[(size_t)r * D + kbase + lc];
                Bs[r][lc + 0] = f2tf32(v.x); Bs[r][lc + 1] = f2tf32(v.y);
                Bs[r][lc + 2] = f2tf32(v.z); Bs[r][lc + 3] = f2tf32(v.w);
            }
        }
        __syncthreads();
        #pragma unroll
        for (int ks = 0; ks < 4; ks++) {
            const int kk = ks * 8;
            uint32_t a0 = As[m0w + gid][kk + tig];
            uint32_t a1 = As[m0w + gid + 8][kk + tig];
            uint32_t a2 = As[m0w + gid][kk + tig + 4];
            uint32_t a3 = As[m0w + gid + 8][kk + tig + 4];
            #pragma unroll
            for (int nt = 0; nt < 7; nt++) {
                uint32_t b0 = Bs[n0w + nt * 8 + gid][kk + tig];
                uint32_t b1 = Bs[n0w + nt * 8 + gid][kk + tig + 4];
                mma_tf32(c[nt], a0, a1, a2, a3, b0, b1);
            }
        }
        __syncthreads();
    }
    float* out = g_Cpart + (size_t)blockIdx.y * NUW;
    #pragma unroll
    for (int nt = 0; nt < 7; nt++) {
        int j0 = n0w + nt * 8 + tig * 2;
        int gr0 = r0 + m0w + gid;
        #pragma unroll
        for (int h = 0; h < 2; h++) {
            int gr = gr0 + 8 * h;
            if (gr < NU) {
                if (j0 < WAY)     out[gr * WAY + j0]     = c[nt][2 * h];
                if (j0 + 1 < WAY) out[gr * WAY + j0 + 1] = c[nt][2 * h + 1];
            }
        }
    }
}

// ---------------- persistent sinkhorn (15 blocks x 512) ----------------
__device__ __forceinline__ void gridbar(int resetSlot) {
    __threadfence();
    __syncthreads();
    if (threadIdx.x == 0) {
        volatile unsigned* vg = &g_barGen;
        unsigned gen = *vg;
        if (atomicAdd(&g_barCount, 1) == (int)gridDim.x - 1) {
            atomicExch(&g_errGlob[resetSlot], 0u);
            *((volatile int*)&g_barCount) = 0;
            __threadfence();
            *vg = gen + 1;
        } else {
            while (*vg == gen) { }
        }
        __threadfence();
    }
    __syncthreads();
}

__global__ void __launch_bounds__(512, 1) k_sinkhorn(float* out, const int* __restrict__ labels) {
    const int t = threadIdx.x, w = t >> 5, lane = t & 31;
    const int blk = blockIdx.x;
    const int rbase = blk * 100;
    __shared__ float scolW[16][128];
    __shared__ float sWerr[16];
    __shared__ float scol[128];
    __shared__ float sErr;

    // ---- phase 0: mn2 (cols striped across blocks) ----
    #pragma unroll
    for (int q = 0; q < 7; q++) {
        int j = blk + 15 * q;
        if (j < WAY) {
            float ss = 0.0f;
            for (int d = t; d < D; d += 512) { float v = g_mus[(size_t)j * D + d]; ss += v * v; }
            ss = blockReduceSum(ss);
            if (t == 0) __stcg(&g_mn2[j], ss);
        }
    }
    gridbar(0);

    // ---- phase 1: K = exp(-lam*dist), Ksum ----
    int cols[4]; bool cv[4]; bool rv[7];
    float Kr[7][4];
    #pragma unroll
    for (int c = 0; c < 4; c++) { cols[c] = lane + 32 * c; cv[c] = (cols[c] < WAY); }
    float mn2c[4];
    #pragma unroll
    for (int c = 0; c < 4; c++) mn2c[c] = cv[c] ? __ldcg(&g_mn2[cols[c]]) : 0.0f;
    float ksl = 0.0f;
    #pragma unroll
    for (int k = 0; k < 7; k++) {
        int r = w + 16 * k;
        rv[k] = (r < 100);
        float z2 = rv[k] ? g_zn2[NL + rbase + r] : 0.0f;
        #pragma unroll
        for (int c = 0; c < 4; c++) {
            float kv = 0.0f;
            if (rv[k] && cv[c]) {
                int idx = (rbase + r) * WAY + cols[c];
                float C = 0.0f;
                #pragma unroll
                for (int s = 0; s < 8; s++) C += g_Cpart[s * NUW + idx];
                float d2 = z2 + mn2c[c] - 2.0f * C;
                kv = expf(-LAMB * sqrtf(fmaxf(d2, 1e-12f)));
            }
            Kr[k][c] = kv;
            ksl += kv;
        }
    }
    ksl = blockReduceSum(ksl);
    if (t == 0) __stcg(&g_KsumPart[blk], ksl);
    gridbar(0);           // also resets err slot 0 for iteration 0
    float ks = 0.0f;
    #pragma unroll
    for (int bb = 0; bb < 15; bb++) ks += __ldcg(&g_KsumPart[bb]);
    float invKs = 1.0f / ks;
    #pragma unroll
    for (int k = 0; k < 7; k++)
        #pragma unroll
        for (int c = 0; c < 4; c++) Kr[k][c] *= invKs;

    // ---- phase 2: iterations (ONE grid barrier each) ----
    float a[7], prev[7], b[4];
    #pragma unroll
    for (int k = 0; k < 7; k++) { a[k] = 1.0f; prev[k] = 0.0f; }
    #pragma unroll
    for (int c = 0; c < 4; c++) b[c] = cv[c] ? 1.0f : 0.0f;

    for (int it = 0; it < MAXIT; ++it) {
        const int p = it & 1;
        float anew[7], rowsum[7];
        float werr = 0.0f;
        #pragma unroll
        for (int k = 0; k < 7; k++) {
            float s = 0.0f;
            #pragma unroll
            for (int c = 0; c < 4; c++) s = fmaf(Kr[k][c], b[c], s);
            #pragma unroll
            for (int off = 16; off; off >>= 1) s += __shfl_xor_sync(0xffffffffu, s, off);
            rowsum[k] = a[k] * s;
            anew[k] = rv[k] ? a[k] / rowsum[k] : 0.0f;
            if (rv[k]) werr = fmaxf(werr, fabsf(prev[k] - rowsum[k]));
        }
        #pragma unroll
        for (int c = 0; c < 4; c++) {
            float s = 0.0f;
            #pragma unroll
            for (int k = 0; k < 7; k++) s = fmaf(Kr[k][c], anew[k], s);
            scolW[w][cols[c]] = s;
        }
        if (lane == 0) sWerr[w] = werr;
        __syncthreads();
        if (t < 128) {
            float s = scolW[0][t];
            #pragma unroll
            for (int ww = 1; ww < 16; ww++) s += scolW[ww][t];
            __stcg(&g_colsumPart[p][blk * 128 + t], s);
        }
        if (t == 0) {
            float e = sWerr[0];
            #pragma unroll
            for (int ww = 1; ww < 16; ww++) e = fmaxf(e, sWerr[ww]);
            atomicMax(&g_errGlob[p], __float_as_uint(e));
        }
        gridbar(1 - p);   // resets err slot for it+1
        if (t < 100) {
            float s = 0.0f;
            #pragma unroll
            for (int bb = 0; bb < 15; bb++) s += __ldcg(&g_colsumPart[p][bb * 128 + t]);
            scol[t] = s;
        }
        if (t == 0) sErr = __uint_as_float(__ldcg(&g_errGlob[p]));
        __syncthreads();
        if (sErr <= 1e-6f) break;      // a,b stay at pre-update values (exact ref semantics)
        #pragma unroll
        for (int k = 0; k < 7; k++) { a[k] = anew[k]; prev[k] = rowsum[k]; }
        #pragma unroll
        for (int c = 0; c < 4; c++) if (cv[c]) b[c] = 15.0f / scol[cols[c]];
    }

    // ---- epilogue: Pu, logP(out), colP partials, acc ----
    float pv[7][4];
    #pragma unroll
    for (int k = 0; k < 7; k++) {
        int r = rbase + w + 16 * k;
        #pragma unroll
        for (int c = 0; c < 4; c++) {
            float p = (rv[k] && cv[c]) ? a[k] * Kr[k][c] * b[c] : 0.0f;
            pv[k][c] = p;
            if (rv[k] && cv[c]) {
                g_Pu[r * WAY + cols[c]] = p;
                if (out) out[r * WAY + cols[c]] = logf(p + 1e-5f);
            }
        }
    }
    __syncthreads();
    #pragma unroll
    for (int c = 0; c < 4; c++) {
        float s = 0.0f;
        #pragma unroll
        for (int k = 0; k < 7; k++) s += pv[k][c];
        scolW[w][cols[c]] = s;
    }
    __syncthreads();
    if (t < 128) {
        float s = scolW[0][t];
        #pragma unroll
        for (int ww = 1; ww < 16; ww++) s += scolW[ww][t];
        __stcg(&g_colPpart[blk * 128 + t], s);
    }
    if (out) {
        int cnt = 0;
        #pragma unroll
        for (int k = 0; k < 7; k++) {
            if (!rv[k]) continue;
            float bv = -1.0f; int bj = WAY;
            #pragma unroll
            for (int c = 0; c < 4; c++)
                if (cv[c] && pv[k][c] > bv) { bv = pv[k][c]; bj = cols[c]; }
            #pragma unroll
            for (int off = 16; off; off >>= 1) {
                float ov = __shfl_xor_sync(0xffffffffu, bv, off);
                int   oj = __shfl_xor_sync(0xffffffffu, bj, off);
                if (ov > bv || (ov == bv && oj < bj)) { bv = ov; bj = oj; }
            }
            if (lane == 0) {
                int r = rbase + w + 16 * k;
                if (bj == labels[NL + r]) cnt++;
            }
        }
        if (lane == 0 && cnt) atomicAdd(&g_accN, cnt);
    }
}

// ===== tensor-core epilogue GEMM: Epart[us][j,d] = sum_u Pu[u,j]*Zu[u,d]
__global__ void __launch_bounds__(256) k_epi() {
    const int n0 = blockIdx.x * 64;
    const int u0 = blockIdx.y * 375;
    const int t  = threadIdx.x;
    const int w  = t >> 5, lane = t & 31;
    const int gid = lane >> 2, tig = lane & 3;
    const int m0w = w * 16;

    __shared__ uint32_t As[16][132];
    __shared__ uint32_t Bs[16][68];

    float c[8][4];
    #pragma unroll
    for (int i = 0; i < 8; i++)
        #pragma unroll
        for (int jj = 0; jj < 4; jj++) c[i][jj] = 0.0f;

    const float* Zu = g_Z + (size_t)NL * D;

    for (int kt = 0; kt < 24; kt++) {
        #pragma unroll
        for (int p = 0; p < 8; p++) {
            int idx = t + 256 * p;
            int k = idx >> 7, m = idx & 127;
            int kg = kt * 16 + k;
            float v = (m < WAY && kg < 375) ? g_Pu[(u0 + kg) * WAY + m] : 0.0f;
            As[k][m] = f2tf32(v);
        }
        {
            int k = t >> 4, nn = (t & 15) * 4;
            int kg = kt * 16 + k;
            float4 v = make_float4(0.f, 0.f, 0.f, 0.f);
            if (kg < 375) v = *(const float4*)&Zu[(size_t)(u0 + kg) * D + n0 + nn];
            Bs[k][nn + 0] = f2tf32(v.x); Bs[k][nn + 1] = f2tf32(v.y);
            Bs[k][nn + 2] = f2tf32(v.z); Bs[k][nn + 3] = f2tf32(v.w);
        }
        __syncthreads();
        #pragma unroll
        for (int ks = 0; ks < 2; ks++) {
            const int kk = ks * 8;
            uint32_t a0 = As[kk + tig][m0w + gid];
            uint32_t a1 = As[kk + tig][m0w + gid + 8];
            uint32_t a2 = As[kk + tig + 4][m0w + gid];
            uint32_t a3 = As[kk + tig + 4][m0w + gid + 8];
            #pragma unroll
            for (int nt = 0; nt < 8; nt++) {
                uint32_t b0 = Bs[kk + tig][nt * 8 + gid];
                uint32_t b1 = Bs[kk + tig + 4][nt * 8 + gid];
                mma_tf32(c[nt], a0, a1, a2, a3, b0, b1);
            }
        }
        __syncthreads();
    }
    float* out = g_Epart + (size_t)blockIdx.y * WAYD;
    #pragma unroll
    for (int nt = 0; nt < 8; nt++) {
        int dcol = n0 + nt * 8 + tig * 2;
        #pragma unroll
        for (int h = 0; h < 2; h++) {
            int j = m0w + gid + 8 * h;
            if (j < WAY) {
                out[(size_t)j * D + dcol]     = c[nt][2 * h];
                out[(size_t)j * D + dcol + 1] = c[nt][2 * h + 1];
            }
        }
    }
}

__global__ void k_update() {
    int idx = blockIdx.x * 256 + threadIdx.x;
    int j = idx >> 12;                    // all 256 threads share one j
    __shared__ float sden;
    if (threadIdx.x == 0) {
        float s = 0.0f;
        #pragma unroll
        for (int bb = 0; bb < 15; bb++) s += g_colPpart[bb * 128 + j];
        sden = 5.0f + s;
    }
    __syncthreads();
    float E = 0.0f;
    #pragma unroll
    for (int s = 0; s < 4; s++) E += g_Epart[s * WAYD + idx];
    float emus = (g_Sl[idx] + E) / sden;
    float m = g_mus[idx];
    g_mus[idx] = m + ALPHAC * (emus - m);
}

__global__ void k_accw(float* __restrict__ out) {
    out[NUW] = (float)g_accN * (1.0f / NU);
}

// ---------------- launch ----------------
extern "C" void kernel_launch(void* const* d_in, const int* in_sizes, int n_in,
                              void* d_out, int out_size) {
    const float* X = (const float*)d_in[0];
    const int* labels = (const int*)d_in[1];
    float* out = (float*)d_out;

    k_pre1<<<NTOT, 256>>>(X);
    k_colmeans<<<D / 64, 256>>>();
    k_pre2<<<NTOT, 256>>>();
    k_Sl<<<WAYD / 256, 256>>>();

    for (int e = 0; e < 21; e++) {
        k_gram<<<dim3(24, 8), 256>>>();
        k_sinkhorn<<<15, 512>>>((e == 20) ? out : (float*)nullptr, labels);
        if (e < 20) {
            k_epi<<<dim3(64, 4), 256>>>();
            k_update<<<WAYD / 256, 256>>>();
        }
    }
    if (out_size > NUW) k_accw<<<1, 1>>>(out);
}

// round 5
// speedup vs baseline: 1.2917x; 1.2917x over previous
#include <cuda_runtime.h>
#include <math.h>
#include <stdint.h>

// ---------------- problem constants ----------------
constexpr int D      = 4096;
constexpr int NTOT   = 2000;
constexpr int NL     = 500;
constexpr int NU     = 1500;
constexpr int WAY    = 100;
constexpr int NUW    = NU * WAY;      // 150000
constexpr int WAYD   = WAY * D;       // 409600
constexpr float LAMB   = 10.0f;
constexpr float ALPHAC = 0.2f;

// ---------------- device scratch ----------------
__device__ float g_X1[NTOT * D];
__device__ float g_Z[NTOT * D];
__device__ float g_zn2[NTOT];
__device__ float g_meanL[D], g_meanU[D];
__device__ float g_Sl[WAYD];
__device__ float g_mus[WAYD];
__device__ float g_mn2[WAY];
__device__ float g_Cpart[8 * NUW];
__device__ float g_Kmat[NUW];
__device__ float g_KsumPart24[24];
__device__ int   g_tileCnt[24];
__device__ float g_Pu[NUW];
__device__ float g_colP[WAY];
__device__ float g_Epart[4 * WAYD];
__device__ float g_errPart[16];
__device__ float g_colsumPart[15 * 128];
__device__ int   g_barCount;
__device__ unsigned g_barGen;
__device__ int   g_accN;

// ---------------- helpers ----------------
__device__ __forceinline__ float blockReduceSum(float v) {
    static __shared__ float sh[32];
    __syncthreads();
    int lane = threadIdx.x & 31, wid = threadIdx.x >> 5;
    #pragma unroll
    for (int off = 16; off; off >>= 1) v += __shfl_xor_sync(0xffffffffu, v, off);
    if (lane == 0) sh[wid] = v;
    __syncthreads();
    int nw = (blockDim.x + 31) >> 5;
    float r = 0.0f;
    if (wid == 0) {
        r = (lane < nw) ? sh[lane] : 0.0f;
        #pragma unroll
        for (int off = 16; off; off >>= 1) r += __shfl_xor_sync(0xffffffffu, r, off);
        if (lane == 0) sh[0] = r;
    }
    __syncthreads();
    return sh[0];
}

__device__ __forceinline__ uint32_t f2tf32(float f) {
    uint32_t r;
    asm("cvt.rna.tf32.f32 %0, %1;" : "=r"(r) : "f"(f));
    return r;
}

__device__ __forceinline__ void mma_tf32(float c[4], uint32_t a0, uint32_t a1,
                                         uint32_t a2, uint32_t a3,
                                         uint32_t b0, uint32_t b1) {
    asm volatile(
        "mma.sync.aligned.m16n8k8.row.col.f32.tf32.tf32.f32 "
        "{%0,%1,%2,%3}, {%4,%5,%6,%7}, {%8,%9}, {%0,%1,%2,%3};\n"
        : "+f"(c[0]), "+f"(c[1]), "+f"(c[2]), "+f"(c[3])
        : "r"(a0), "r"(a1), "r"(a2), "r"(a3), "r"(b0), "r"(b1));
}

// ---------------- preprocessing ----------------
__global__ void k_pre1(const float* __restrict__ X) {
    int row = blockIdx.x, t = threadIdx.x;
    __shared__ float buf[D];
    float ss = 0.0f;
    for (int d = t; d < D; d += blockDim.x) {
        float v = sqrtf(X[(size_t)row * D + d] + 1e-6f);
        buf[d] = v; ss += v * v;
    }
    ss = blockReduceSum(ss);
    float inv = 1.0f / fmaxf(sqrtf(ss), 1e-12f);
    for (int d = t; d < D; d += blockDim.x) g_X1[(size_t)row * D + d] = buf[d] * inv;
}

__global__ void k_colmeans() {
    int lane = threadIdx.x & 63;
    int part = threadIdx.x >> 6;         // 0..3
    int d = blockIdx.x * 64 + lane;
    __shared__ float sh[4][64];
    float sL = 0.0f;
    for (int i = part * 125; i < (part + 1) * 125; i++) sL += g_X1[(size_t)i * D + d];
    sh[part][lane] = sL;
    __syncthreads();
    if (part == 0)
        g_meanL[d] = (sh[0][lane] + sh[1][lane] + sh[2][lane] + sh[3][lane]) * (1.0f / NL);
    __syncthreads();
    float sU = 0.0f;
    for (int i = NL + part * 375; i < NL + (part + 1) * 375; i++) sU += g_X1[(size_t)i * D + d];
    sh[part][lane] = sU;
    __syncthreads();
    if (part == 0)
        g_meanU[d] = (sh[0][lane] + sh[1][lane] + sh[2][lane] + sh[3][lane]) * (1.0f / NU);
}

__global__ void k_pre2() {
    int row = blockIdx.x, t = threadIdx.x;
    __shared__ float buf[D];
    const float* mean = (row < NL) ? g_meanL : g_meanU;
    float ss = 0.0f;
    for (int d = t; d < D; d += blockDim.x) {
        float v = g_X1[(size_t)row * D + d] - mean[d];
        buf[d] = v; ss += v * v;
    }
    ss = blockReduceSum(ss);
    float inv = 1.0f / fmaxf(sqrtf(ss), 1e-12f);
    if (t == 0) g_zn2[row] = ss * inv * inv;
    for (int d = t; d < D; d += blockDim.x) g_Z[(size_t)row * D + d] = buf[d] * inv;
}

__global__ void k_Sl() {
    int idx = blockIdx.x * blockDim.x + threadIdx.x;
    if (idx >= WAYD) return;
    int c = idx >> 12, d = idx & (D - 1);
    float s = 0.0f;
    #pragma unroll
    for (int k = 0; k < 5; k++) s += g_Z[(size_t)(k * WAY + c) * D + d];
    g_Sl[idx] = s;
    g_mus[idx] = s * 0.2f;
    if (idx < 24) g_tileCnt[idx] = 0;
}

// ---------------- per-iteration kernels ----------------
__global__ void k_mn2() {
    int j = blockIdx.x;
    float ss = 0.0f;
    for (int d = threadIdx.x; d < D; d += blockDim.x) {
        float v = g_mus[(size_t)j * D + d]; ss += v * v;
    }
    ss = blockReduceSum(ss);
    if (threadIdx.x == 0) g_mn2[j] = ss;
}

// ===== tensor-core gram + fused exp tail
// grid (24 m-blocks, 8 k-splits), 256 threads (8 warps)
// block tile M=64, N=112 (pad of 100), warps 4x2 -> warp tile m16 x n56
// The 8th-arriving k-split block of each m-block combines the 8 partials,
// computes K = exp(-lam*dist) and a per-m-block Ksum partial.
__global__ void __launch_bounds__(256) k_gram() {
    const int r0 = blockIdx.x * 64;
    const int k0 = blockIdx.y * 512;
    const int t  = threadIdx.x;
    const int w  = t >> 5, lane = t & 31;
    const int gid = lane >> 2, tig = lane & 3;
    const int mw = w >> 1;            // 0..3
    const int nw = w & 1;             // 0..1
    const int m0w = mw * 16;
    const int n0w = nw * 56;

    __shared__ uint32_t As[64][33];   // [m][k] tf32 bits
    __shared__ uint32_t Bs[112][33];  // [n][k]

    float c[7][4];
    #pragma unroll
    for (int i = 0; i < 7; i++)
        #pragma unroll
        for (int jj = 0; jj < 4; jj++) c[i][jj] = 0.0f;

    const float* Zu = g_Z + (size_t)NL * D;
    const int lr = t >> 3;            // 0..31
    const int lc = (t & 7) * 4;       // k group

    for (int kt = 0; kt < 512; kt += 32) {
        const int kbase = k0 + kt;
        #pragma unroll
        for (int p = 0; p < 2; p++) {
            int r = lr + 32 * p;
            float4 v = make_float4(0.f, 0.f, 0.f, 0.f);
            if (r0 + r < NU) v = *(const float4*)&Zu[(size_t)(r0 + r) * D + kbase + lc];
            As[r][lc + 0] = f2tf32(v.x); As[r][lc + 1] = f2tf32(v.y);
            As[r][lc + 2] = f2tf32(v.z); As[r][lc + 3] = f2tf32(v.w);
        }
        #pragma unroll
        for (int p = 0; p < 4; p++) {
            int r = lr + 32 * p;
            if (r < 112) {
                float4 v = make_float4(0.f, 0.f, 0.f, 0.f);
                if (r < WAY) v = *(const float4*)&g_mus[(size_t)r * D + kbase + lc];
                Bs[r][lc + 0] = f2tf32(v.x); Bs[r][lc + 1] = f2tf32(v.y);
                Bs[r][lc + 2] = f2tf32(v.z); Bs[r][lc + 3] = f2tf32(v.w);
            }
        }
        __syncthreads();
        #pragma unroll
        for (int ks = 0; ks < 4; ks++) {
            const int kk = ks * 8;
            uint32_t a0 = As[m0w + gid][kk + tig];
            uint32_t a1 = As[m0w + gid + 8][kk + tig];
            uint32_t a2 = As[m0w + gid][kk + tig + 4];
            uint32_t a3 = As[m0w + gid + 8][kk + tig + 4];
            #pragma unroll
            for (int nt = 0; nt < 7; nt++) {
                uint32_t b0 = Bs[n0w + nt * 8 + gid][kk + tig];
                uint32_t b1 = Bs[n0w + nt * 8 + gid][kk + tig + 4];
                mma_tf32(c[nt], a0, a1, a2, a3, b0, b1);
            }
        }
        __syncthreads();
    }
    float* outp = g_Cpart + (size_t)blockIdx.y * NUW;
    #pragma unroll
    for (int nt = 0; nt < 7; nt++) {
        int j0 = n0w + nt * 8 + tig * 2;
        int gr0 = r0 + m0w + gid;
        #pragma unroll
        for (int h = 0; h < 2; h++) {
            int gr = gr0 + 8 * h;
            if (gr < NU) {
                if (j0 < WAY)     outp[gr * WAY + j0]     = c[nt][2 * h];
                if (j0 + 1 < WAY) outp[gr * WAY + j0 + 1] = c[nt][2 * h + 1];
            }
        }
    }

    // ---- fused exp tail: last-arriving k-split block of this m-block ----
    __shared__ int sLast;
    __syncthreads();
    if (t == 0) {
        __threadfence();
        int cval = atomicAdd(&g_tileCnt[blockIdx.x], 1);
        int last = (cval == 7);
        if (last) g_tileCnt[blockIdx.x] = 0;   // reset for next epoch
        sLast = last;
    }
    __syncthreads();
    if (!sLast) return;
    __threadfence();                            // acquire: see peers' Cpart stores

    float ksl = 0.0f;
    for (int e = t; e < 64 * WAY; e += 256) {
        int rr = e / WAY;
        int j  = e - rr * WAY;
        int gr = r0 + rr;
        if (gr < NU) {
            int idx = gr * WAY + j;
            float C = 0.0f;
            #pragma unroll
            for (int s = 0; s < 8; s++) C += g_Cpart[s * NUW + idx];
            float d2 = g_zn2[NL + gr] + g_mn2[j] - 2.0f * C;
            float kv = expf(-LAMB * sqrtf(fmaxf(d2, 1e-12f)));
            g_Kmat[idx] = kv;
            ksl += kv;
        }
    }
    ksl = blockReduceSum(ksl);
    if (t == 0) g_KsumPart24[blockIdx.x] = ksl;
}

// ---------------- persistent sinkhorn (15 blocks x 512) ----------------
__device__ __forceinline__ void gridbar() {
    __threadfence();
    __syncthreads();
    if (threadIdx.x == 0) {
        volatile unsigned* vg = &g_barGen;
        unsigned gen = *vg;
        if (atomicAdd(&g_barCount, 1) == (int)gridDim.x - 1) {
            *((volatile int*)&g_barCount) = 0;
            __threadfence();
            *vg = gen + 1;
        } else {
            while (*vg == gen) { }
        }
        __threadfence();
    }
    __syncthreads();
}

__global__ void __launch_bounds__(512, 1) k_sinkhorn() {
    const int t = threadIdx.x, w = t >> 5, lane = t & 31;
    const int blk = blockIdx.x;
    const int rbase = blk * 100;
    __shared__ float sWerr[16];
    __shared__ float scolW[16][128];
    float ksum = 0.0f;
    #pragma unroll
    for (int m = 0; m < 24; m++) ksum += __ldcg(&g_KsumPart24[m]);
    const float invKs = 1.0f / ksum;
    float Kr[7][4], a[7], prev[7], b[4], rowsum[7];
    bool rv[7], cv[4];
    int cols[4];
    #pragma unroll
    for (int c = 0; c < 4; c++) {
        int j = lane + 32 * c;
        cols[c] = j; cv[c] = (j < WAY); b[c] = cv[c] ? 1.0f : 0.0f;
    }
    #pragma unroll
    for (int k = 0; k < 7; k++) {
        int r = w + 16 * k;
        rv[k] = (r < 100); a[k] = 1.0f; prev[k] = 0.0f; rowsum[k] = 1.0f;
        #pragma unroll
        for (int c = 0; c < 4; c++)
            Kr[k][c] = (rv[k] && cv[c]) ? g_Kmat[(rbase + r) * WAY + cols[c]] * invKs : 0.0f;
    }

    for (int it = 0; it < 1000; ++it) {
        float werr = 0.0f;
        #pragma unroll
        for (int k = 0; k < 7; k++) {
            float s = 0.0f;
            #pragma unroll
            for (int c = 0; c < 4; c++) s = fmaf(Kr[k][c], b[c], s);
            #pragma unroll
            for (int off = 16; off; off >>= 1) s += __shfl_xor_sync(0xffffffffu, s, off);
            rowsum[k] = a[k] * s;
            if (rv[k]) werr = fmaxf(werr, fabsf(prev[k] - rowsum[k]));
        }
        if (lane == 0) sWerr[w] = werr;
        __syncthreads();
        if (t == 0) {
            float e = sWerr[0];
            #pragma unroll
            for (int ww = 1; ww < 16; ww++) e = fmaxf(e, sWerr[ww]);
            __stcg(&g_errPart[blk], e);
        }
        gridbar();
        float err = __ldcg(&g_errPart[0]);
        for (int bb = 1; bb < 15; bb++) err = fmaxf(err, __ldcg(&g_errPart[bb]));
        if (err <= 1e-6f) break;
        #pragma unroll
        for (int k = 0; k < 7; k++) {
            if (rv[k]) { a[k] = a[k] / rowsum[k]; prev[k] = rowsum[k]; }
        }
        #pragma unroll
        for (int c = 0; c < 4; c++) {
            float s = 0.0f;
            #pragma unroll
            for (int k = 0; k < 7; k++) s = fmaf(Kr[k][c], a[k], s);
            scolW[w][cols[c]] = cv[c] ? s : 0.0f;
        }
        __syncthreads();
        if (t < 128) {
            float s = scolW[0][t];
            #pragma unroll
            for (int ww = 1; ww < 16; ww++) s += scolW[ww][t];
            __stcg(&g_colsumPart[blk * 128 + t], s);
        }
        gridbar();
        #pragma unroll
        for (int c = 0; c < 4; c++) {
            if (cv[c]) {
                float cs = __ldcg(&g_colsumPart[cols[c]]);
                for (int bb = 1; bb < 15; bb++) cs += __ldcg(&g_colsumPart[bb * 128 + cols[c]]);
                b[c] = 15.0f / cs;
            }
        }
    }
    #pragma unroll
    for (int k = 0; k < 7; k++) {
        if (!rv[k]) continue;
        int r = rbase + w + 16 * k;
        #pragma unroll
        for (int c = 0; c < 4; c++)
            if (cv[c]) g_Pu[r * WAY + cols[c]] = a[k] * Kr[k][c] * b[c];
    }
}

// column sums of Pu (deterministic)
__global__ void k_colP() {
    int j = blockIdx.x;
    float s = 0.0f;
    for (int i = threadIdx.x; i < NU; i += blockDim.x) s += g_Pu[i * WAY + j];
    s = blockReduceSum(s);
    if (threadIdx.x == 0) g_colP[j] = s;
}

// ===== tensor-core epilogue GEMM: Epart[us][j,d] = sum_u Pu[u,j]*Zu[u,d]
__global__ void __launch_bounds__(256) k_epi() {
    const int n0 = blockIdx.x * 64;
    const int u0 = blockIdx.y * 375;
    const int t  = threadIdx.x;
    const int w  = t >> 5, lane = t & 31;
    const int gid = lane >> 2, tig = lane & 3;
    const int m0w = w * 16;

    __shared__ uint32_t As[16][132];
    __shared__ uint32_t Bs[16][68];

    float c[8][4];
    #pragma unroll
    for (int i = 0; i < 8; i++)
        #pragma unroll
        for (int jj = 0; jj < 4; jj++) c[i][jj] = 0.0f;

    const float* Zu = g_Z + (size_t)NL * D;

    for (int kt = 0; kt < 24; kt++) {
        #pragma unroll
        for (int p = 0; p < 8; p++) {
            int idx = t + 256 * p;
            int k = idx >> 7, m = idx & 127;
            int kg = kt * 16 + k;
            float v = (m < WAY && kg < 375) ? g_Pu[(u0 + kg) * WAY + m] : 0.0f;
            As[k][m] = f2tf32(v);
        }
        {
            int k = t >> 4, nn = (t & 15) * 4;
            int kg = kt * 16 + k;
            float4 v = make_float4(0.f, 0.f, 0.f, 0.f);
            if (kg < 375) v = *(const float4*)&Zu[(size_t)(u0 + kg) * D + n0 + nn];
            Bs[k][nn + 0] = f2tf32(v.x); Bs[k][nn + 1] = f2tf32(v.y);
            Bs[k][nn + 2] = f2tf32(v.z); Bs[k][nn + 3] = f2tf32(v.w);
        }
        __syncthreads();
        #pragma unroll
        for (int ks = 0; ks < 2; ks++) {
            const int kk = ks * 8;
            uint32_t a0 = As[kk + tig][m0w + gid];
            uint32_t a1 = As[kk + tig][m0w + gid + 8];
            uint32_t a2 = As[kk + tig + 4][m0w + gid];
            uint32_t a3 = As[kk + tig + 4][m0w + gid + 8];
            #pragma unroll
            for (int nt = 0; nt < 8; nt++) {
                uint32_t b0 = Bs[kk + tig][nt * 8 + gid];
                uint32_t b1 = Bs[kk + tig + 4][nt * 8 + gid];
                mma_tf32(c[nt], a0, a1, a2, a3, b0, b1);
            }
        }
        __syncthreads();
    }
    float* outp = g_Epart + (size_t)blockIdx.y * WAYD;
    #pragma unroll
    for (int nt = 0; nt < 8; nt++) {
        int dcol = n0 + nt * 8 + tig * 2;
        #pragma unroll
        for (int h = 0; h < 2; h++) {
            int j = m0w + gid + 8 * h;
            if (j < WAY) {
                outp[(size_t)j * D + dcol]     = c[nt][2 * h];
                outp[(size_t)j * D + dcol + 1] = c[nt][2 * h + 1];
            }
        }
    }
}

__global__ void k_update() {
    int idx = blockIdx.x * blockDim.x + threadIdx.x;
    if (idx >= WAYD) return;
    int j = idx >> 12;
    float E = 0.0f;
    #pragma unroll
    for (int s = 0; s < 4; s++) E += g_Epart[s * WAYD + idx];
    float denom = 5.0f + g_colP[j];
    float emus = (g_Sl[idx] + E) / denom;
    float m = g_mus[idx];
    g_mus[idx] = m + ALPHAC * (emus - m);
}

// ---------------- output ----------------
__global__ void k_out(float* __restrict__ out) {
    int idx = blockIdx.x * blockDim.x + threadIdx.x;
    if (idx == 0) g_accN = 0;
    if (idx < NUW) out[idx] = logf(g_Pu[idx] + 1e-5f);
}

__global__ void k_acc(const int* __restrict__ labels) {
    int i = blockIdx.x * blockDim.x + threadIdx.x;
    if (i >= NU) return;
    const float* row = g_Pu + i * WAY;
    float best = row[0]; int bj = 0;
    for (int j = 1; j < WAY; j++) {
        float v = row[j];
        if (v > best) { best = v; bj = j; }
    }
    if (bj == labels[NL + i]) atomicAdd(&g_accN, 1);
}

__global__ void k_accw(float* __restrict__ out) {
    out[NUW] = (float)g_accN * (1.0f / NU);
}

// ---------------- launch ----------------
extern "C" void kernel_launch(void* const* d_in, const int* in_sizes, int n_in,
                              void* d_out, int out_size) {
    const float* X = (const float*)d_in[0];
    const int* labels = (const int*)d_in[1];
    float* out = (float*)d_out;

    k_pre1<<<NTOT, 256>>>(X);
    k_colmeans<<<D / 64, 256>>>();
    k_pre2<<<NTOT, 256>>>();
    k_Sl<<<WAYD / 256, 256>>>();

    for (int e = 0; e < 21; e++) {
        k_mn2<<<WAY, 256>>>();
        k_gram<<<dim3(24, 8), 256>>>();
        k_sinkhorn<<<15, 512>>>();
        if (e < 20) {
            k_colP<<<WAY, 128>>>();
            k_epi<<<dim3(64, 4), 256>>>();
            k_update<<<WAYD / 256, 256>>>();
        }
    }
    k_out<<<(NUW + 255) / 256, 256>>>(out);
    k_acc<<<(NU + 255) / 256, 256>>>(labels);
    if (out_size > NUW) k_accw<<<1, 1>>>(out);
}

// round 6
// speedup vs baseline: 1.5564x; 1.2049x over previous
#include <cuda_runtime.h>
#include <math.h>
#include <stdint.h>

// ---------------- problem constants ----------------
constexpr int D      = 4096;
constexpr int NTOT   = 2000;
constexpr int NL     = 500;
constexpr int NU     = 1500;
constexpr int WAY    = 100;
constexpr int NUW    = NU * WAY;      // 150000
constexpr int WAYD   = WAY * D;       // 409600
constexpr float LAMB   = 10.0f;
constexpr float ALPHAC = 0.2f;
constexpr int EXPK_BLOCKS = (NUW + 255) / 256;   // 586

// ---------------- device scratch ----------------
__device__ float g_X1[NTOT * D];
__device__ float g_Z[NTOT * D];
__device__ float g_zn2[NTOT];
__device__ float g_meanL[D], g_meanU[D];
__device__ float g_Sl[WAYD];
__device__ float g_mus[WAYD];
__device__ float g_mn2[WAY];
__device__ float g_Cpart[8 * NUW];
__device__ float g_Kmat[NUW];
__device__ float g_Kpart[600];
__device__ float g_Pu[NUW];
__device__ float g_colP[WAY];
__device__ float g_Epart[4 * WAYD];
__device__ unsigned g_errGlob[2];
__device__ float g_colsumPart[2][15 * 128];
__device__ int   g_barCount;
__device__ unsigned g_barGen;
__device__ int   g_accN;

// ---------------- helpers ----------------
__device__ __forceinline__ float blockReduceSum(float v) {
    static __shared__ float sh[32];
    __syncthreads();
    int lane = threadIdx.x & 31, wid = threadIdx.x >> 5;
    #pragma unroll
    for (int off = 16; off; off >>= 1) v += __shfl_xor_sync(0xffffffffu, v, off);
    if (lane == 0) sh[wid] = v;
    __syncthreads();
    int nw = (blockDim.x + 31) >> 5;
    float r = 0.0f;
    if (wid == 0) {
        r = (lane < nw) ? sh[lane] : 0.0f;
        #pragma unroll
        for (int off = 16; off; off >>= 1) r += __shfl_xor_sync(0xffffffffu, r, off);
        if (lane == 0) sh[0] = r;
    }
    __syncthreads();
    return sh[0];
}

__device__ __forceinline__ uint32_t f2tf32(float f) {
    uint32_t r;
    asm("cvt.rna.tf32.f32 %0, %1;" : "=r"(r) : "f"(f));
    return r;
}

__device__ __forceinline__ void mma_tf32(float c[4], uint32_t a0, uint32_t a1,
                                         uint32_t a2, uint32_t a3,
                                         uint32_t b0, uint32_t b1) {
    asm volatile(
        "mma.sync.aligned.m16n8k8.row.col.f32.tf32.tf32.f32 "
        "{%0,%1,%2,%3}, {%4,%5,%6,%7}, {%8,%9}, {%0,%1,%2,%3};\n"
        : "+f"(c[0]), "+f"(c[1]), "+f"(c[2]), "+f"(c[3])
        : "r"(a0), "r"(a1), "r"(a2), "r"(a3), "r"(b0), "r"(b1));
}

// ---------------- preprocessing ----------------
__global__ void k_pre1(const float* __restrict__ X) {
    int row = blockIdx.x, t = threadIdx.x;
    __shared__ float buf[D];
    float ss = 0.0f;
    for (int d = t; d < D; d += blockDim.x) {
        float v = sqrtf(X[(size_t)row * D + d] + 1e-6f);
        buf[d] = v; ss += v * v;
    }
    ss = blockReduceSum(ss);
    float inv = 1.0f / fmaxf(sqrtf(ss), 1e-12f);
    for (int d = t; d < D; d += blockDim.x) g_X1[(size_t)row * D + d] = buf[d] * inv;
}

__global__ void k_colmeans() {
    int lane = threadIdx.x & 63;
    int part = threadIdx.x >> 6;         // 0..3
    int d = blockIdx.x * 64 + lane;
    __shared__ float sh[4][64];
    float sL = 0.0f;
    for (int i = part * 125; i < (part + 1) * 125; i++) sL += g_X1[(size_t)i * D + d];
    sh[part][lane] = sL;
    __syncthreads();
    if (part == 0)
        g_meanL[d] = (sh[0][lane] + sh[1][lane] + sh[2][lane] + sh[3][lane]) * (1.0f / NL);
    __syncthreads();
    float sU = 0.0f;
    for (int i = NL + part * 375; i < NL + (part + 1) * 375; i++) sU += g_X1[(size_t)i * D + d];
    sh[part][lane] = sU;
    __syncthreads();
    if (part == 0)
        g_meanU[d] = (sh[0][lane] + sh[1][lane] + sh[2][lane] + sh[3][lane]) * (1.0f / NU);
}

__global__ void k_pre2() {
    int row = blockIdx.x, t = threadIdx.x;
    __shared__ float buf[D];
    const float* mean = (row < NL) ? g_meanL : g_meanU;
    float ss = 0.0f;
    for (int d = t; d < D; d += blockDim.x) {
        float v = g_X1[(size_t)row * D + d] - mean[d];
        buf[d] = v; ss += v * v;
    }
    ss = blockReduceSum(ss);
    float inv = 1.0f / fmaxf(sqrtf(ss), 1e-12f);
    if (t == 0) g_zn2[row] = ss * inv * inv;
    for (int d = t; d < D; d += blockDim.x) g_Z[(size_t)row * D + d] = buf[d] * inv;
}

__global__ void k_Sl() {
    int idx = blockIdx.x * blockDim.x + threadIdx.x;
    if (idx >= WAYD) return;
    int c = idx >> 12, d = idx & (D - 1);
    float s = 0.0f;
    #pragma unroll
    for (int k = 0; k < 5; k++) s += g_Z[(size_t)(k * WAY + c) * D + d];
    g_Sl[idx] = s;
    g_mus[idx] = s * 0.2f;
}

// ---------------- per-iteration kernels ----------------
__global__ void k_mn2() {
    int j = blockIdx.x;
    float ss = 0.0f;
    for (int d = threadIdx.x; d < D; d += blockDim.x) {
        float v = g_mus[(size_t)j * D + d]; ss += v * v;
    }
    ss = blockReduceSum(ss);
    if (threadIdx.x == 0) g_mn2[j] = ss;
}

// ===== tensor-core gram: Cpart[ks][i,j] = sum over 512-k-chunk Zu[i,k]*mus[j,k]
__global__ void __launch_bounds__(256) k_gram() {
    const int r0 = blockIdx.x * 64;
    const int k0 = blockIdx.y * 512;
    const int t  = threadIdx.x;
    const int w  = t >> 5, lane = t & 31;
    const int gid = lane >> 2, tig = lane & 3;
    const int mw = w >> 1;            // 0..3
    const int nw = w & 1;             // 0..1
    const int m0w = mw * 16;
    const int n0w = nw * 56;

    __shared__ uint32_t As[64][33];   // [m][k] tf32 bits
    __shared__ uint32_t Bs[112][33];  // [n][k]

    float c[7][4];
    #pragma unroll
    for (int i = 0; i < 7; i++)
        #pragma unroll
        for (int jj = 0; jj < 4; jj++) c[i][jj] = 0.0f;

    const float* Zu = g_Z + (size_t)NL * D;
    const int lr = t >> 3;            // 0..31
    const int lc = (t & 7) * 4;       // k group

    for (int kt = 0; kt < 512; kt += 32) {
        const int kbase = k0 + kt;
        #pragma unroll
        for (int p = 0; p < 2; p++) {
            int r = lr + 32 * p;
            float4 v = make_float4(0.f, 0.f, 0.f, 0.f);
            if (r0 + r < NU) v = *(const float4*)&Zu[(size_t)(r0 + r) * D + kbase + lc];
            As[r][lc + 0] = f2tf32(v.x); As[r][lc + 1] = f2tf32(v.y);
            As[r][lc + 2] = f2tf32(v.z); As[r][lc + 3] = f2tf32(v.w);
        }
        #pragma unroll
        for (int p = 0; p < 4; p++) {
            int r = lr + 32 * p;
            if (r < 112) {
                float4 v = make_float4(0.f, 0.f, 0.f, 0.f);
                if (r < WAY) v = *(const float4*)&g_mus[(size_t)r * D + kbase + lc];
                Bs[r][lc + 0] = f2tf32(v.x); Bs[r][lc + 1] = f2tf32(v.y);
                Bs[r][lc + 2] = f2tf32(v.z); Bs[r][lc + 3] = f2tf32(v.w);
            }
        }
        __syncthreads();
        #pragma unroll
        for (int ks = 0; ks < 4; ks++) {
            const int kk = ks * 8;
            uint32_t a0 = As[m0w + gid][kk + tig];
            uint32_t a1 = As[m0w + gid + 8][kk + tig];
            uint32_t a2 = As[m0w + gid][kk + tig + 4];
            uint32_t a3 = As[m0w + gid + 8][kk + tig + 4];
            #pragma unroll
            for (int nt = 0; nt < 7; nt++) {
                uint32_t b0 = Bs[n0w + nt * 8 + gid][kk + tig];
                uint32_t b1 = Bs[n0w + nt * 8 + gid][kk + tig + 4];
                mma_tf32(c[nt], a0, a1, a2, a3, b0, b1);
            }
        }
        __syncthreads();
    }
    float* out = g_Cpart + (size_t)blockIdx.y * NUW;
    #pragma unroll
    for (int nt = 0; nt < 7; nt++) {
        int j0 = n0w + nt * 8 + tig * 2;
        int gr0 = r0 + m0w + gid;
        #pragma unroll
        for (int h = 0; h < 2; h++) {
            int gr = gr0 + 8 * h;
            if (gr < NU) {
                if (j0 < WAY)     out[gr * WAY + j0]     = c[nt][2 * h];
                if (j0 + 1 < WAY) out[gr * WAY + j0 + 1] = c[nt][2 * h + 1];
            }
        }
    }
}

// K = exp(-lam*dist); block partial sums; also resets sinkhorn err slots
__global__ void k_expK() {
    int idx = blockIdx.x * blockDim.x + threadIdx.x;
    if (idx < 2) g_errGlob[idx] = 0u;
    float kv = 0.0f;
    if (idx < NUW) {
        int i = idx / WAY, j = idx - i * WAY;
        float c = 0.0f;
        #pragma unroll
        for (int s = 0; s < 8; s++) c += g_Cpart[s * NUW + idx];
        float d2 = g_zn2[NL + i] + g_mn2[j] - 2.0f * c;
        float dist = sqrtf(fmaxf(d2, 1e-12f));
        kv = expf(-LAMB * dist);
        g_Kmat[idx] = kv;
    }
    float bs = blockReduceSum(kv);
    if (threadIdx.x == 0) g_Kpart[blockIdx.x] = bs;
}

// ---------------- persistent sinkhorn (15 blocks x 512), 1 barrier/iter ----------------
__device__ __forceinline__ void gridbar(int resetSlot) {
    __threadfence();
    __syncthreads();
    if (threadIdx.x == 0) {
        volatile unsigned* vg = &g_barGen;
        unsigned gen = *vg;
        if (atomicAdd(&g_barCount, 1) == (int)gridDim.x - 1) {
            atomicExch(&g_errGlob[resetSlot], 0u);
            *((volatile int*)&g_barCount) = 0;
            __threadfence();
            *vg = gen + 1;
        } else {
            while (*vg == gen) { }
        }
        __threadfence();
    }
    __syncthreads();
}

__global__ void __launch_bounds__(512, 1) k_sinkhorn() {
    const int t = threadIdx.x, w = t >> 5, lane = t & 31;
    const int blk = blockIdx.x;
    const int rbase = blk * 100;
    __shared__ float sWerr[16];
    __shared__ float scolW[16][128];

    // Ksum from expK partials (identical fixed-order computation in every block)
    float ks = 0.0f;
    for (int i = t; i < EXPK_BLOCKS; i += 512) ks += __ldcg(&g_Kpart[i]);
    ks = blockReduceSum(ks);
    const float invKs = 1.0f / ks;

    float Kr[7][4], a[7], prev[7], b[4];
    bool rv[7], cv[4];
    int cols[4];
    #pragma unroll
    for (int c = 0; c < 4; c++) {
        int j = lane + 32 * c;
        cols[c] = j; cv[c] = (j < WAY); b[c] = cv[c] ? 1.0f : 0.0f;
    }
    #pragma unroll
    for (int k = 0; k < 7; k++) {
        int r = w + 16 * k;
        rv[k] = (r < 100); a[k] = 1.0f; prev[k] = 0.0f;
        #pragma unroll
        for (int c = 0; c < 4; c++)
            Kr[k][c] = (rv[k] && cv[c]) ? g_Kmat[(rbase + r) * WAY + cols[c]] * invKs : 0.0f;
    }

    for (int it = 0; it < 1000; ++it) {
        const int p = it & 1;
        float rowsum[7], anew[7];
        float werr = 0.0f;
        #pragma unroll
        for (int k = 0; k < 7; k++) {
            float s = 0.0f;
            #pragma unroll
            for (int c = 0; c < 4; c++) s = fmaf(Kr[k][c], b[c], s);
            #pragma unroll
            for (int off = 16; off; off >>= 1) s += __shfl_xor_sync(0xffffffffu, s, off);
            rowsum[k] = a[k] * s;
            anew[k] = rv[k] ? a[k] / rowsum[k] : 0.0f;
            if (rv[k]) werr = fmaxf(werr, fabsf(prev[k] - rowsum[k]));
        }
        #pragma unroll
        for (int c = 0; c < 4; c++) {
            float s = 0.0f;
            #pragma unroll
            for (int k = 0; k < 7; k++) s = fmaf(Kr[k][c], anew[k], s);
            scolW[w][cols[c]] = cv[c] ? s : 0.0f;
        }
        if (lane == 0) sWerr[w] = werr;
        __syncthreads();
        if (t < 128) {
            float s = scolW[0][t];
            #pragma unroll
            for (int ww = 1; ww < 16; ww++) s += scolW[ww][t];
            __stcg(&g_colsumPart[p][blk * 128 + t], s);
        }
        if (t == 0) {
            float e = sWerr[0];
            #pragma unroll
            for (int ww = 1; ww < 16; ww++) e = fmaxf(e, sWerr[ww]);
            atomicMax(&g_errGlob[p], __float_as_uint(e));
        }
        gridbar(1 - p);                 // resets err slot for it+1
        float err = __uint_as_float(__ldcg(&g_errGlob[p]));
        float csum[4];
        #pragma unroll
        for (int c = 0; c < 4; c++) {
            float cs = __ldcg(&g_colsumPart[p][cols[c]]);
            #pragma unroll
            for (int bb = 1; bb < 15; bb++) cs += __ldcg(&g_colsumPart[p][bb * 128 + cols[c]]);
            csum[c] = cs;
        }
        if (err <= 1e-6f) break;        // a,b stay pre-update: exact reference semantics
        #pragma unroll
        for (int k = 0; k < 7; k++) { a[k] = anew[k]; prev[k] = rowsum[k]; }
        #pragma unroll
        for (int c = 0; c < 4; c++) if (cv[c]) b[c] = 15.0f / csum[c];
    }

    #pragma unroll
    for (int k = 0; k < 7; k++) {
        if (!rv[k]) continue;
        int r = rbase + w + 16 * k;
        #pragma unroll
        for (int c = 0; c < 4; c++)
            if (cv[c]) g_Pu[r * WAY + cols[c]] = a[k] * Kr[k][c] * b[c];
    }
}

// column sums of Pu (deterministic)
__global__ void k_colP() {
    int j = blockIdx.x;
    float s = 0.0f;
    for (int i = threadIdx.x; i < NU; i += blockDim.x) s += g_Pu[i * WAY + j];
    s = blockReduceSum(s);
    if (threadIdx.x == 0) g_colP[j] = s;
}

// ===== tensor-core epilogue GEMM: Epart[us][j,d] = sum_u Pu[u,j]*Zu[u,d]
__global__ void __launch_bounds__(256) k_epi() {
    const int n0 = blockIdx.x * 64;
    const int u0 = blockIdx.y * 375;
    const int t  = threadIdx.x;
    const int w  = t >> 5, lane = t & 31;
    const int gid = lane >> 2, tig = lane & 3;
    const int m0w = w * 16;

    __shared__ uint32_t As[16][132];
    __shared__ uint32_t Bs[16][68];

    float c[8][4];
    #pragma unroll
    for (int i = 0; i < 8; i++)
        #pragma unroll
        for (int jj = 0; jj < 4; jj++) c[i][jj] = 0.0f;

    const float* Zu = g_Z + (size_t)NL * D;

    for (int kt = 0; kt < 24; kt++) {
        #pragma unroll
        for (int p = 0; p < 8; p++) {
            int idx = t + 256 * p;
            int k = idx >> 7, m = idx & 127;
            int kg = kt * 16 + k;
            float v = (m < WAY && kg < 375) ? g_Pu[(u0 + kg) * WAY + m] : 0.0f;
            As[k][m] = f2tf32(v);
        }
        {
            int k = t >> 4, nn = (t & 15) * 4;
            int kg = kt * 16 + k;
            float4 v = make_float4(0.f, 0.f, 0.f, 0.f);
            if (kg < 375) v = *(const float4*)&Zu[(size_t)(u0 + kg) * D + n0 + nn];
            Bs[k][nn + 0] = f2tf32(v.x); Bs[k][nn + 1] = f2tf32(v.y);
            Bs[k][nn + 2] = f2tf32(v.z); Bs[k][nn + 3] = f2tf32(v.w);
        }
        __syncthreads();
        #pragma unroll
        for (int ks = 0; ks < 2; ks++) {
            const int kk = ks * 8;
            uint32_t a0 = As[kk + tig][m0w + gid];
            uint32_t a1 = As[kk + tig][m0w + gid + 8];
            uint32_t a2 = As[kk + tig + 4][m0w + gid];
            uint32_t a3 = As[kk + tig + 4][m0w + gid + 8];
            #pragma unroll
            for (int nt = 0; nt < 8; nt++) {
                uint32_t b0 = Bs[kk + tig][nt * 8 + gid];
                uint32_t b1 = Bs[kk + tig + 4][nt * 8 + gid];
                mma_tf32(c[nt], a0, a1, a2, a3, b0, b1);
            }
        }
        __syncthreads();
    }
    float* outp = g_Epart + (size_t)blockIdx.y * WAYD;
    #pragma unroll
    for (int nt = 0; nt < 8; nt++) {
        int dcol = n0 + nt * 8 + tig * 2;
        #pragma unroll
        for (int h = 0; h < 2; h++) {
            int j = m0w + gid + 8 * h;
            if (j < WAY) {
                outp[(size_t)j * D + dcol]     = c[nt][2 * h];
                outp[(size_t)j * D + dcol + 1] = c[nt][2 * h + 1];
            }
        }
    }
}

__global__ void k_update() {
    int idx = blockIdx.x * blockDim.x + threadIdx.x;
    if (idx >= WAYD) return;
    int j = idx >> 12;
    float E = 0.0f;
    #pragma unroll
    for (int s = 0; s < 4; s++) E += g_Epart[s * WAYD + idx];
    float denom = 5.0f + g_colP[j];
    float emus = (g_Sl[idx] + E) / denom;
    float m = g_mus[idx];
    g_mus[idx] = m + ALPHAC * (emus - m);
}

// ---------------- output ----------------
__global__ void k_out(float* __restrict__ out) {
    int idx = blockIdx.x * blockDim.x + threadIdx.x;
    if (idx == 0) g_accN = 0;
    if (idx < NUW) out[idx] = logf(g_Pu[idx] + 1e-5f);
}

__global__ void k_acc(const int* __restrict__ labels) {
    int i = blockIdx.x * blockDim.x + threadIdx.x;
    if (i >= NU) return;
    const float* row = g_Pu + i * WAY;
    float best = row[0]; int bj = 0;
    for (int j = 1; j < WAY; j++) {
        float v = row[j];
        if (v > best) { best = v; bj = j; }
    }
    if (bj == labels[NL + i]) atomicAdd(&g_accN, 1);
}

__global__ void k_accw(float* __restrict__ out) {
    out[NUW] = (float)g_accN * (1.0f / NU);
}

// ---------------- launch ----------------
extern "C" void kernel_launch(void* const* d_in, const int* in_sizes, int n_in,
                              void* d_out, int out_size) {
    const float* X = (const float*)d_in[0];
    const int* labels = (const int*)d_in[1];
    float* out = (float*)d_out;

    k_pre1<<<NTOT, 256>>>(X);
    k_colmeans<<<D / 64, 256>>>();
    k_pre2<<<NTOT, 256>>>();
    k_Sl<<<WAYD / 256, 256>>>();

    for (int e = 0; e < 21; e++) {
        k_mn2<<<WAY, 256>>>();
        k_gram<<<dim3(24, 8), 256>>>();
        k_expK<<<EXPK_BLOCKS, 256>>>();
        k_sinkhorn<<<15, 512>>>();
        if (e < 20) {
            k_colP<<<WAY, 128>>>();
            k_epi<<<dim3(64, 4), 256>>>();
            k_update<<<WAYD / 256, 256>>>();
        }
    }
    k_out<<<(NUW + 255) / 256, 256>>>(out);
    k_acc<<<(NU + 255) / 256, 256>>>(labels);
    if (out_size > NUW) k_accw<<<1, 1>>>(out);
}

// round 7
// speedup vs baseline: 1.5849x; 1.0183x over previous
#include <cuda_runtime.h>
#include <math.h>
#include <stdint.h>

// ---------------- problem constants ----------------
constexpr int D      = 4096;
constexpr int NTOT   = 2000;
constexpr int NL     = 500;
constexpr int NU     = 1500;
constexpr int WAY    = 100;
constexpr int NUW    = NU * WAY;      // 150000
constexpr int WAYD   = WAY * D;       // 409600
constexpr float LAMB   = 10.0f;
constexpr float ALPHAC = 0.2f;
constexpr int EXPK_BLOCKS = (NUW + 255) / 256;   // 586

// ---------------- device scratch ----------------
__device__ float g_X1[NTOT * D];
__device__ float g_Z[NTOT * D];
__device__ float g_zn2[NTOT];
__device__ float g_meanL[D], g_meanU[D];
__device__ float g_Sl[WAYD];
__device__ float g_mus[WAYD];
__device__ float g_mn2[WAY];
__device__ float g_Cpart[8 * NUW];
__device__ float g_Kmat[NUW];
__device__ float g_Kpart[600];
__device__ float g_Pu[NUW];
__device__ float g_colPpart[15 * 128];
__device__ float g_Epart[4 * WAYD];
__device__ unsigned g_errGlob[2];
__device__ float g_colsumPart[2][15 * 128];
__device__ int   g_barCount;
__device__ unsigned g_barGen;
__device__ int   g_accN;

// ---------------- helpers ----------------
__device__ __forceinline__ float blockReduceSum(float v) {
    static __shared__ float sh[32];
    __syncthreads();
    int lane = threadIdx.x & 31, wid = threadIdx.x >> 5;
    #pragma unroll
    for (int off = 16; off; off >>= 1) v += __shfl_xor_sync(0xffffffffu, v, off);
    if (lane == 0) sh[wid] = v;
    __syncthreads();
    int nw = (blockDim.x + 31) >> 5;
    float r = 0.0f;
    if (wid == 0) {
        r = (lane < nw) ? sh[lane] : 0.0f;
        #pragma unroll
        for (int off = 16; off; off >>= 1) r += __shfl_xor_sync(0xffffffffu, r, off);
        if (lane == 0) sh[0] = r;
    }
    __syncthreads();
    return sh[0];
}

__device__ __forceinline__ uint32_t f2tf32(float f) {
    uint32_t r;
    asm("cvt.rna.tf32.f32 %0, %1;" : "=r"(r) : "f"(f));
    return r;
}

__device__ __forceinline__ void mma_tf32(float c[4], uint32_t a0, uint32_t a1,
                                         uint32_t a2, uint32_t a3,
                                         uint32_t b0, uint32_t b1) {
    asm volatile(
        "mma.sync.aligned.m16n8k8.row.col.f32.tf32.tf32.f32 "
        "{%0,%1,%2,%3}, {%4,%5,%6,%7}, {%8,%9}, {%0,%1,%2,%3};\n"
        : "+f"(c[0]), "+f"(c[1]), "+f"(c[2]), "+f"(c[3])
        : "r"(a0), "r"(a1), "r"(a2), "r"(a3), "r"(b0), "r"(b1));
}

// ---------------- preprocessing ----------------
__global__ void k_pre1(const float* __restrict__ X) {
    int row = blockIdx.x, t = threadIdx.x;
    __shared__ float buf[D];
    float ss = 0.0f;
    for (int d = t; d < D; d += blockDim.x) {
        float v = sqrtf(X[(size_t)row * D + d] + 1e-6f);
        buf[d] = v; ss += v * v;
    }
    ss = blockReduceSum(ss);
    float inv = 1.0f / fmaxf(sqrtf(ss), 1e-12f);
    for (int d = t; d < D; d += blockDim.x) g_X1[(size_t)row * D + d] = buf[d] * inv;
}

__global__ void k_colmeans() {
    int lane = threadIdx.x & 63;
    int part = threadIdx.x >> 6;         // 0..3
    int d = blockIdx.x * 64 + lane;
    __shared__ float sh[4][64];
    float sL = 0.0f;
    for (int i = part * 125; i < (part + 1) * 125; i++) sL += g_X1[(size_t)i * D + d];
    sh[part][lane] = sL;
    __syncthreads();
    if (part == 0)
        g_meanL[d] = (sh[0][lane] + sh[1][lane] + sh[2][lane] + sh[3][lane]) * (1.0f / NL);
    __syncthreads();
    float sU = 0.0f;
    for (int i = NL + part * 375; i < NL + (part + 1) * 375; i++) sU += g_X1[(size_t)i * D + d];
    sh[part][lane] = sU;
    __syncthreads();
    if (part == 0)
        g_meanU[d] = (sh[0][lane] + sh[1][lane] + sh[2][lane] + sh[3][lane]) * (1.0f / NU);
}

__global__ void k_pre2() {
    int row = blockIdx.x, t = threadIdx.x;
    __shared__ float buf[D];
    const float* mean = (row < NL) ? g_meanL : g_meanU;
    float ss = 0.0f;
    for (int d = t; d < D; d += blockDim.x) {
        float v = g_X1[(size_t)row * D + d] - mean[d];
        buf[d] = v; ss += v * v;
    }
    ss = blockReduceSum(ss);
    float inv = 1.0f / fmaxf(sqrtf(ss), 1e-12f);
    if (t == 0) g_zn2[row] = ss * inv * inv;
    for (int d = t; d < D; d += blockDim.x) g_Z[(size_t)row * D + d] = buf[d] * inv;
}

// one block per class: Sl, mus0, mn2
__global__ void k_Sl() {
    int c = blockIdx.x, t = threadIdx.x;
    float ss = 0.0f;
    #pragma unroll
    for (int q = 0; q < 16; q++) {
        int d = t + 256 * q;
        float s = 0.0f;
        #pragma unroll
        for (int k = 0; k < 5; k++) s += g_Z[(size_t)(k * WAY + c) * D + d];
        g_Sl[c * D + d] = s;
        float m = s * 0.2f;
        g_mus[c * D + d] = m;
        ss += m * m;
    }
    ss = blockReduceSum(ss);
    if (t == 0) g_mn2[c] = ss;
}

// ===== tensor-core gram: Cpart[ks][i,j] = sum over 512-k-chunk Zu[i,k]*mus[j,k]
__global__ void __launch_bounds__(256) k_gram() {
    const int r0 = blockIdx.x * 64;
    const int k0 = blockIdx.y * 512;
    const int t  = threadIdx.x;
    const int w  = t >> 5, lane = t & 31;
    const int gid = lane >> 2, tig = lane & 3;
    const int mw = w >> 1;            // 0..3
    const int nw = w & 1;             // 0..1
    const int m0w = mw * 16;
    const int n0w = nw * 56;

    __shared__ uint32_t As[64][33];   // [m][k] tf32 bits
    __shared__ uint32_t Bs[112][33];  // [n][k]

    float c[7][4];
    #pragma unroll
    for (int i = 0; i < 7; i++)
        #pragma unroll
        for (int jj = 0; jj < 4; jj++) c[i][jj] = 0.0f;

    const float* Zu = g_Z + (size_t)NL * D;
    const int lr = t >> 3;            // 0..31
    const int lc = (t & 7) * 4;       // k group

    for (int kt = 0; kt < 512; kt += 32) {
        const int kbase = k0 + kt;
        #pragma unroll
        for (int p = 0; p < 2; p++) {
            int r = lr + 32 * p;
            float4 v = make_float4(0.f, 0.f, 0.f, 0.f);
            if (r0 + r < NU) v = *(const float4*)&Zu[(size_t)(r0 + r) * D + kbase + lc];
            As[r][lc + 0] = f2tf32(v.x); As[r][lc + 1] = f2tf32(v.y);
            As[r][lc + 2] = f2tf32(v.z); As[r][lc + 3] = f2tf32(v.w);
        }
        #pragma unroll
        for (int p = 0; p < 4; p++) {
            int r = lr + 32 * p;
            if (r < 112) {
                float4 v = make_float4(0.f, 0.f, 0.f, 0.f);
                if (r < WAY) v = *(const float4*)&g_mus[(size_t)r * D + kbase + lc];
                Bs[r][lc + 0] = f2tf32(v.x); Bs[r][lc + 1] = f2tf32(v.y);
                Bs[r][lc + 2] = f2tf32(v.z); Bs[r][lc + 3] = f2tf32(v.w);
            }
        }
        __syncthreads();
        #pragma unroll
        for (int ks = 0; ks < 4; ks++) {
            const int kk = ks * 8;
            uint32_t a0 = As[m0w + gid][kk + tig];
            uint32_t a1 = As[m0w + gid + 8][kk + tig];
            uint32_t a2 = As[m0w + gid][kk + tig + 4];
            uint32_t a3 = As[m0w + gid + 8][kk + tig + 4];
            #pragma unroll
            for (int nt = 0; nt < 7; nt++) {
                uint32_t b0 = Bs[n0w + nt * 8 + gid][kk + tig];
                uint32_t b1 = Bs[n0w + nt * 8 + gid][kk + tig + 4];
                mma_tf32(c[nt], a0, a1, a2, a3, b0, b1);
            }
        }
        __syncthreads();
    }
    float* out = g_Cpart + (size_t)blockIdx.y * NUW;
    #pragma unroll
    for (int nt = 0; nt < 7; nt++) {
        int j0 = n0w + nt * 8 + tig * 2;
        int gr0 = r0 + m0w + gid;
        #pragma unroll
        for (int h = 0; h < 2; h++) {
            int gr = gr0 + 8 * h;
            if (gr < NU) {
                if (j0 < WAY)     out[gr * WAY + j0]     = c[nt][2 * h];
                if (j0 + 1 < WAY) out[gr * WAY + j0 + 1] = c[nt][2 * h + 1];
            }
        }
    }
}

// K = exp(-lam*dist); block partial sums; also resets sinkhorn err slots
__global__ void k_expK() {
    int idx = blockIdx.x * blockDim.x + threadIdx.x;
    if (idx < 2) g_errGlob[idx] = 0u;
    float kv = 0.0f;
    if (idx < NUW) {
        int i = idx / WAY, j = idx - i * WAY;
        float c = 0.0f;
        #pragma unroll
        for (int s = 0; s < 8; s++) c += g_Cpart[s * NUW + idx];
        float d2 = g_zn2[NL + i] + g_mn2[j] - 2.0f * c;
        float dist = sqrtf(fmaxf(d2, 1e-12f));
        kv = expf(-LAMB * dist);
        g_Kmat[idx] = kv;
    }
    float bs = blockReduceSum(kv);
    if (threadIdx.x == 0) g_Kpart[blockIdx.x] = bs;
}

// ---------------- persistent sinkhorn (15 blocks x 512), 1 barrier/iter ----------------
__device__ __forceinline__ void gridbar(int resetSlot) {
    __threadfence();
    __syncthreads();
    if (threadIdx.x == 0) {
        volatile unsigned* vg = &g_barGen;
        unsigned gen = *vg;
        if (atomicAdd(&g_barCount, 1) == (int)gridDim.x - 1) {
            atomicExch(&g_errGlob[resetSlot], 0u);
            *((volatile int*)&g_barCount) = 0;
            __threadfence();
            *vg = gen + 1;
        } else {
            while (*vg == gen) { }
        }
        __threadfence();
    }
    __syncthreads();
}

__global__ void __launch_bounds__(512, 1) k_sinkhorn() {
    const int t = threadIdx.x, w = t >> 5, lane = t & 31;
    const int blk = blockIdx.x;
    const int rbase = blk * 100;
    __shared__ float sWerr[16];
    __shared__ float scolW[16][128];

    // Ksum from expK partials (identical fixed-order computation in every block)
    float ks = 0.0f;
    for (int i = t; i < EXPK_BLOCKS; i += 512) ks += __ldcg(&g_Kpart[i]);
    ks = blockReduceSum(ks);
    const float invKs = 1.0f / ks;

    float Kr[7][4], a[7], prev[7], b[4];
    bool rv[7], cv[4];
    int cols[4];
    #pragma unroll
    for (int c = 0; c < 4; c++) {
        int j = lane + 32 * c;
        cols[c] = j; cv[c] = (j < WAY); b[c] = cv[c] ? 1.0f : 0.0f;
    }
    #pragma unroll
    for (int k = 0; k < 7; k++) {
        int r = w + 16 * k;
        rv[k] = (r < 100); a[k] = 1.0f; prev[k] = 0.0f;
        #pragma unroll
        for (int c = 0; c < 4; c++)
            Kr[k][c] = (rv[k] && cv[c]) ? g_Kmat[(rbase + r) * WAY + cols[c]] * invKs : 0.0f;
    }

    for (int it = 0; it < 1000; ++it) {
        const int p = it & 1;
        float rowsum[7], anew[7];
        float werr = 0.0f;
        #pragma unroll
        for (int k = 0; k < 7; k++) {
            float s = 0.0f;
            #pragma unroll
            for (int c = 0; c < 4; c++) s = fmaf(Kr[k][c], b[c], s);
            #pragma unroll
            for (int off = 16; off; off >>= 1) s += __shfl_xor_sync(0xffffffffu, s, off);
            rowsum[k] = a[k] * s;
            anew[k] = rv[k] ? a[k] / rowsum[k] : 0.0f;
            if (rv[k]) werr = fmaxf(werr, fabsf(prev[k] - rowsum[k]));
        }
        #pragma unroll
        for (int c = 0; c < 4; c++) {
            float s = 0.0f;
            #pragma unroll
            for (int k = 0; k < 7; k++) s = fmaf(Kr[k][c], anew[k], s);
            scolW[w][cols[c]] = cv[c] ? s : 0.0f;
        }
        if (lane == 0) sWerr[w] = werr;
        __syncthreads();
        if (t < 128) {
            float s = scolW[0][t];
            #pragma unroll
            for (int ww = 1; ww < 16; ww++) s += scolW[ww][t];
            __stcg(&g_colsumPart[p][blk * 128 + t], s);
        }
        if (t == 0) {
            float e = sWerr[0];
            #pragma unroll
            for (int ww = 1; ww < 16; ww++) e = fmaxf(e, sWerr[ww]);
            atomicMax(&g_errGlob[p], __float_as_uint(e));
        }
        gridbar(1 - p);                 // resets err slot for it+1
        float err = __uint_as_float(__ldcg(&g_errGlob[p]));
        float csum[4];
        #pragma unroll
        for (int c = 0; c < 4; c++) {
            float cs = __ldcg(&g_colsumPart[p][cols[c]]);
            #pragma unroll
            for (int bb = 1; bb < 15; bb++) cs += __ldcg(&g_colsumPart[p][bb * 128 + cols[c]]);
            csum[c] = cs;
        }
        if (err <= 1e-6f) break;        // a,b stay pre-update: exact reference semantics
        #pragma unroll
        for (int k = 0; k < 7; k++) { a[k] = anew[k]; prev[k] = rowsum[k]; }
        #pragma unroll
        for (int c = 0; c < 4; c++) if (cv[c]) b[c] = 15.0f / csum[c];
    }

    // epilogue: write Pu + per-block column-sum partials (for k_update's denom)
    float colacc[4] = {0.f, 0.f, 0.f, 0.f};
    #pragma unroll
    for (int k = 0; k < 7; k++) {
        if (!rv[k]) continue;
        int r = rbase + w + 16 * k;
        #pragma unroll
        for (int c = 0; c < 4; c++) {
            if (cv[c]) {
                float pval = a[k] * Kr[k][c] * b[c];
                g_Pu[r * WAY + cols[c]] = pval;
                colacc[c] += pval;
            }
        }
    }
    __syncthreads();
    #pragma unroll
    for (int c = 0; c < 4; c++) scolW[w][cols[c]] = cv[c] ? colacc[c] : 0.0f;
    __syncthreads();
    if (t < 128) {
        float s = scolW[0][t];
        #pragma unroll
        for (int ww = 1; ww < 16; ww++) s += scolW[ww][t];
        __stcg(&g_colPpart[blk * 128 + t], s);
    }
}

// ===== tensor-core epilogue GEMM: Epart[us][j,d] = sum_u Pu[u,j]*Zu[u,d]
__global__ void __launch_bounds__(256) k_epi() {
    const int n0 = blockIdx.x * 64;
    const int u0 = blockIdx.y * 375;
    const int t  = threadIdx.x;
    const int w  = t >> 5, lane = t & 31;
    const int gid = lane >> 2, tig = lane & 3;
    const int m0w = w * 16;

    __shared__ uint32_t As[16][132];
    __shared__ uint32_t Bs[16][68];

    float c[8][4];
    #pragma unroll
    for (int i = 0; i < 8; i++)
        #pragma unroll
        for (int jj = 0; jj < 4; jj++) c[i][jj] = 0.0f;

    const float* Zu = g_Z + (size_t)NL * D;

    for (int kt = 0; kt < 24; kt++) {
        #pragma unroll
        for (int p = 0; p < 8; p++) {
            int idx = t + 256 * p;
            int k = idx >> 7, m = idx & 127;
            int kg = kt * 16 + k;
            float v = (m < WAY && kg < 375) ? g_Pu[(u0 + kg) * WAY + m] : 0.0f;
            As[k][m] = f2tf32(v);
        }
        {
            int k = t >> 4, nn = (t & 15) * 4;
            int kg = kt * 16 + k;
            float4 v = make_float4(0.f, 0.f, 0.f, 0.f);
            if (kg < 375) v = *(const float4*)&Zu[(size_t)(u0 + kg) * D + n0 + nn];
            Bs[k][nn + 0] = f2tf32(v.x); Bs[k][nn + 1] = f2tf32(v.y);
            Bs[k][nn + 2] = f2tf32(v.z); Bs[k][nn + 3] = f2tf32(v.w);
        }
        __syncthreads();
        #pragma unroll
        for (int ks = 0; ks < 2; ks++) {
            const int kk = ks * 8;
            uint32_t a0 = As[kk + tig][m0w + gid];
            uint32_t a1 = As[kk + tig][m0w + gid + 8];
            uint32_t a2 = As[kk + tig + 4][m0w + gid];
            uint32_t a3 = As[kk + tig + 4][m0w + gid + 8];
            #pragma unroll
            for (int nt = 0; nt < 8; nt++) {
                uint32_t b0 = Bs[kk + tig][nt * 8 + gid];
                uint32_t b1 = Bs[kk + tig + 4][nt * 8 + gid];
                mma_tf32(c[nt], a0, a1, a2, a3, b0, b1);
            }
        }
        __syncthreads();
    }
    float* outp = g_Epart + (size_t)blockIdx.y * WAYD;
    #pragma unroll
    for (int nt = 0; nt < 8; nt++) {
        int dcol = n0 + nt * 8 + tig * 2;
        #pragma unroll
        for (int h = 0; h < 2; h++) {
            int j = m0w + gid + 8 * h;
            if (j < WAY) {
                outp[(size_t)j * D + dcol]     = c[nt][2 * h];
                outp[(size_t)j * D + dcol + 1] = c[nt][2 * h + 1];
            }
        }
    }
}

// one block per class: mus update + mn2 for next epoch
__global__ void __launch_bounds__(512) k_update() {
    const int j = blockIdx.x, t = threadIdx.x;
    __shared__ float sden;
    if (t == 0) {
        float s = 0.0f;
        #pragma unroll
        for (int bb = 0; bb < 15; bb++) s += g_colPpart[bb * 128 + j];
        sden = 5.0f + s;
    }
    __syncthreads();
    const float invden = 1.0f / sden;
    float ss = 0.0f;
    #pragma unroll
    for (int q = 0; q < 8; q++) {
        int idx = j * D + t + 512 * q;
        float E = 0.0f;
        #pragma unroll
        for (int s = 0; s < 4; s++) E += g_Epart[s * WAYD + idx];
        float emus = (g_Sl[idx] + E) * invden;
        float m = g_mus[idx];
        m = m + ALPHAC * (emus - m);
        g_mus[idx] = m;
        ss += m * m;
    }
    ss = blockReduceSum(ss);
    if (t == 0) g_mn2[j] = ss;
}

// ---------------- output ----------------
__global__ void k_out(float* __restrict__ out) {
    int idx = blockIdx.x * blockDim.x + threadIdx.x;
    if (idx == 0) g_accN = 0;
    if (idx < NUW) out[idx] = logf(g_Pu[idx] + 1e-5f);
}

__global__ void k_acc(const int* __restrict__ labels) {
    int i = blockIdx.x * blockDim.x + threadIdx.x;
    if (i >= NU) return;
    const float* row = g_Pu + i * WAY;
    float best = row[0]; int bj = 0;
    for (int j = 1; j < WAY; j++) {
        float v = row[j];
        if (v > best) { best = v; bj = j; }
    }
    if (bj == labels[NL + i]) atomicAdd(&g_accN, 1);
}

__global__ void k_accw(float* __restrict__ out) {
    out[NUW] = (float)g_accN * (1.0f / NU);
}

// ---------------- launch ----------------
extern "C" void kernel_launch(void* const* d_in, const int* in_sizes, int n_in,
                              void* d_out, int out_size) {
    const float* X = (const float*)d_in[0];
    const int* labels = (const int*)d_in[1];
    float* out = (float*)d_out;

    k_pre1<<<NTOT, 256>>>(X);
    k_colmeans<<<D / 64, 256>>>();
    k_pre2<<<NTOT, 256>>>();
    k_Sl<<<WAY, 256>>>();

    for (int e = 0; e < 21; e++) {
        k_gram<<<dim3(24, 8), 256>>>();
        k_expK<<<EXPK_BLOCKS, 256>>>();
        k_sinkhorn<<<15, 512>>>();
        if (e < 20) {
            k_epi<<<dim3(64, 4), 256>>>();
            k_update<<<WAY, 512>>>();
        }
    }
    k_out<<<(NUW + 255) / 256, 256>>>(out);
    k_acc<<<(NU + 255) / 256, 256>>>(labels);
    if (out_size > NUW) k_accw<<<1, 1>>>(out);
}

// round 8
// speedup vs baseline: 1.6023x; 1.0110x over previous
#include <cuda_runtime.h>
#include <math.h>
#include <stdint.h>

// ---------------- problem constants ----------------
constexpr int D      = 4096;
constexpr int NTOT   = 2000;
constexpr int NL     = 500;
constexpr int NU     = 1500;
constexpr int WAY    = 100;
constexpr int NUW    = NU * WAY;      // 150000
constexpr int WAYD   = WAY * D;       // 409600
constexpr float LAMB   = 10.0f;
constexpr float ALPHAC = 0.2f;
constexpr int EXPK_BLOCKS = (NUW + 255) / 256;   // 586
constexpr int SKB = 8;                 // sinkhorn cluster blocks
constexpr int ROWS_W = 12;             // rows per warp (128 warps * 12 = 1536 >= 1500)

// ---------------- device scratch ----------------
__device__ float g_X1[NTOT * D];
__device__ float g_Z[NTOT * D];
__device__ float g_zn2[NTOT];
__device__ float g_meanL[D], g_meanU[D];
__device__ float g_Sl[WAYD];
__device__ float g_mus[WAYD];
__device__ float g_mn2[WAY];
__device__ float g_Cpart[8 * NUW];
__device__ float g_Kmat[NUW];
__device__ float g_Kpart[600];
__device__ float g_Pu[NUW];
__device__ float g_colPpart[SKB * 128];
__device__ float g_Epart[4 * WAYD];
__device__ int   g_accN;

// ---------------- helpers ----------------
__device__ __forceinline__ float blockReduceSum(float v) {
    static __shared__ float sh[32];
    __syncthreads();
    int lane = threadIdx.x & 31, wid = threadIdx.x >> 5;
    #pragma unroll
    for (int off = 16; off; off >>= 1) v += __shfl_xor_sync(0xffffffffu, v, off);
    if (lane == 0) sh[wid] = v;
    __syncthreads();
    int nw = (blockDim.x + 31) >> 5;
    float r = 0.0f;
    if (wid == 0) {
        r = (lane < nw) ? sh[lane] : 0.0f;
        #pragma unroll
        for (int off = 16; off; off >>= 1) r += __shfl_xor_sync(0xffffffffu, r, off);
        if (lane == 0) sh[0] = r;
    }
    __syncthreads();
    return sh[0];
}

__device__ __forceinline__ uint32_t f2tf32(float f) {
    uint32_t r;
    asm("cvt.rna.tf32.f32 %0, %1;" : "=r"(r) : "f"(f));
    return r;
}

__device__ __forceinline__ void mma_tf32(float c[4], uint32_t a0, uint32_t a1,
                                         uint32_t a2, uint32_t a3,
                                         uint32_t b0, uint32_t b1) {
    asm volatile(
        "mma.sync.aligned.m16n8k8.row.col.f32.tf32.tf32.f32 "
        "{%0,%1,%2,%3}, {%4,%5,%6,%7}, {%8,%9}, {%0,%1,%2,%3};\n"
        : "+f"(c[0]), "+f"(c[1]), "+f"(c[2]), "+f"(c[3])
        : "r"(a0), "r"(a1), "r"(a2), "r"(a3), "r"(b0), "r"(b1));
}

__device__ __forceinline__ float dsmem_ld(uint32_t local_addr, uint32_t rank) {
    float v;
    asm volatile(
        "{\n\t"
        ".reg .b32 ra;\n\t"
        "mapa.shared::cluster.u32 ra, %1, %2;\n\t"
        "ld.shared::cluster.f32 %0, [ra];\n\t"
        "}"
        : "=f"(v) : "r"(local_addr), "r"(rank));
    return v;
}

#define CLUSTER_SYNC() do { \
    asm volatile("barrier.cluster.arrive.aligned;" ::: "memory"); \
    asm volatile("barrier.cluster.wait.aligned;" ::: "memory"); \
} while (0)

// ---------------- preprocessing ----------------
__global__ void k_pre1(const float* __restrict__ X) {
    int row = blockIdx.x, t = threadIdx.x;
    __shared__ float buf[D];
    float ss = 0.0f;
    for (int d = t; d < D; d += blockDim.x) {
        float v = sqrtf(X[(size_t)row * D + d] + 1e-6f);
        buf[d] = v; ss += v * v;
    }
    ss = blockReduceSum(ss);
    float inv = 1.0f / fmaxf(sqrtf(ss), 1e-12f);
    for (int d = t; d < D; d += blockDim.x) g_X1[(size_t)row * D + d] = buf[d] * inv;
}

__global__ void k_colmeans() {
    int lane = threadIdx.x & 63;
    int part = threadIdx.x >> 6;         // 0..3
    int d = blockIdx.x * 64 + lane;
    __shared__ float sh[4][64];
    float sL = 0.0f;
    for (int i = part * 125; i < (part + 1) * 125; i++) sL += g_X1[(size_t)i * D + d];
    sh[part][lane] = sL;
    __syncthreads();
    if (part == 0)
        g_meanL[d] = (sh[0][lane] + sh[1][lane] + sh[2][lane] + sh[3][lane]) * (1.0f / NL);
    __syncthreads();
    float sU = 0.0f;
    for (int i = NL + part * 375; i < NL + (part + 1) * 375; i++) sU += g_X1[(size_t)i * D + d];
    sh[part][lane] = sU;
    __syncthreads();
    if (part == 0)
        g_meanU[d] = (sh[0][lane] + sh[1][lane] + sh[2][lane] + sh[3][lane]) * (1.0f / NU);
}

__global__ void k_pre2() {
    int row = blockIdx.x, t = threadIdx.x;
    __shared__ float buf[D];
    const float* mean = (row < NL) ? g_meanL : g_meanU;
    float ss = 0.0f;
    for (int d = t; d < D; d += blockDim.x) {
        float v = g_X1[(size_t)row * D + d] - mean[d];
        buf[d] = v; ss += v * v;
    }
    ss = blockReduceSum(ss);
    float inv = 1.0f / fmaxf(sqrtf(ss), 1e-12f);
    if (t == 0) g_zn2[row] = ss * inv * inv;
    for (int d = t; d < D; d += blockDim.x) g_Z[(size_t)row * D + d] = buf[d] * inv;
}

// one block per class: Sl, mus0, mn2
__global__ void k_Sl() {
    int c = blockIdx.x, t = threadIdx.x;
    float ss = 0.0f;
    #pragma unroll
    for (int q = 0; q < 16; q++) {
        int d = t + 256 * q;
        float s = 0.0f;
        #pragma unroll
        for (int k = 0; k < 5; k++) s += g_Z[(size_t)(k * WAY + c) * D + d];
        g_Sl[c * D + d] = s;
        float m = s * 0.2f;
        g_mus[c * D + d] = m;
        ss += m * m;
    }
    ss = blockReduceSum(ss);
    if (t == 0) g_mn2[c] = ss;
}

// ===== tensor-core gram: Cpart[ks][i,j] = sum over 512-k-chunk Zu[i,k]*mus[j,k]
__global__ void __launch_bounds__(256) k_gram() {
    const int r0 = blockIdx.x * 64;
    const int k0 = blockIdx.y * 512;
    const int t  = threadIdx.x;
    const int w  = t >> 5, lane = t & 31;
    const int gid = lane >> 2, tig = lane & 3;
    const int mw = w >> 1;            // 0..3
    const int nw = w & 1;             // 0..1
    const int m0w = mw * 16;
    const int n0w = nw * 56;

    __shared__ uint32_t As[64][33];   // [m][k] tf32 bits
    __shared__ uint32_t Bs[112][33];  // [n][k]

    float c[7][4];
    #pragma unroll
    for (int i = 0; i < 7; i++)
        #pragma unroll
        for (int jj = 0; jj < 4; jj++) c[i][jj] = 0.0f;

    const float* Zu = g_Z + (size_t)NL * D;
    const int lr = t >> 3;            // 0..31
    const int lc = (t & 7) * 4;       // k group

    for (int kt = 0; kt < 512; kt += 32) {
        const int kbase = k0 + kt;
        #pragma unroll
        for (int p = 0; p < 2; p++) {
            int r = lr + 32 * p;
            float4 v = make_float4(0.f, 0.f, 0.f, 0.f);
            if (r0 + r < NU) v = *(const float4*)&Zu[(size_t)(r0 + r) * D + kbase + lc];
            As[r][lc + 0] = f2tf32(v.x); As[r][lc + 1] = f2tf32(v.y);
            As[r][lc + 2] = f2tf32(v.z); As[r][lc + 3] = f2tf32(v.w);
        }
        #pragma unroll
        for (int p = 0; p < 4; p++) {
            int r = lr + 32 * p;
            if (r < 112) {
                float4 v = make_float4(0.f, 0.f, 0.f, 0.f);
                if (r < WAY) v = *(const float4*)&g_mus[(size_t)r * D + kbase + lc];
                Bs[r][lc + 0] = f2tf32(v.x); Bs[r][lc + 1] = f2tf32(v.y);
                Bs[r][lc + 2] = f2tf32(v.z); Bs[r][lc + 3] = f2tf32(v.w);
            }
        }
        __syncthreads();
        #pragma unroll
        for (int ks = 0; ks < 4; ks++) {
            const int kk = ks * 8;
            uint32_t a0 = As[m0w + gid][kk + tig];
            uint32_t a1 = As[m0w + gid + 8][kk + tig];
            uint32_t a2 = As[m0w + gid][kk + tig + 4];
            uint32_t a3 = As[m0w + gid + 8][kk + tig + 4];
            #pragma unroll
            for (int nt = 0; nt < 7; nt++) {
                uint32_t b0 = Bs[n0w + nt * 8 + gid][kk + tig];
                uint32_t b1 = Bs[n0w + nt * 8 + gid][kk + tig + 4];
                mma_tf32(c[nt], a0, a1, a2, a3, b0, b1);
            }
        }
        __syncthreads();
    }
    float* out = g_Cpart + (size_t)blockIdx.y * NUW;
    #pragma unroll
    for (int nt = 0; nt < 7; nt++) {
        int j0 = n0w + nt * 8 + tig * 2;
        int gr0 = r0 + m0w + gid;
        #pragma unroll
        for (int h = 0; h < 2; h++) {
            int gr = gr0 + 8 * h;
            if (gr < NU) {
                if (j0 < WAY)     out[gr * WAY + j0]     = c[nt][2 * h];
                if (j0 + 1 < WAY) out[gr * WAY + j0 + 1] = c[nt][2 * h + 1];
            }
        }
    }
}

// K = exp(-lam*dist); block partial sums
__global__ void k_expK() {
    int idx = blockIdx.x * blockDim.x + threadIdx.x;
    float kv = 0.0f;
    if (idx < NUW) {
        int i = idx / WAY, j = idx - i * WAY;
        float c = 0.0f;
        #pragma unroll
        for (int s = 0; s < 8; s++) c += g_Cpart[s * NUW + idx];
        float d2 = g_zn2[NL + i] + g_mn2[j] - 2.0f * c;
        float dist = sqrtf(fmaxf(d2, 1e-12f));
        kv = expf(-LAMB * dist);
        g_Kmat[idx] = kv;
    }
    float bs = blockReduceSum(kv);
    if (threadIdx.x == 0) g_Kpart[blockIdx.x] = bs;
}

// ---------------- cluster-based persistent sinkhorn (8 CTAs x 512) ----------------
__global__ void __cluster_dims__(SKB, 1, 1) __launch_bounds__(512, 1) k_sinkhorn() {
    const int t = threadIdx.x, w = t >> 5, lane = t & 31;
    const int blk = blockIdx.x;           // == cluster rank (single cluster)
    const int gw  = blk * 16 + w;         // global warp 0..127
    const int rbase = gw * ROWS_W;
    __shared__ float scolW[16][128];
    __shared__ float sWerr[16];
    __shared__ float colsumBuf[2][128];
    __shared__ float errBuf[2];
    __shared__ float sbcast[128];
    __shared__ float sErrSh;

    // Ksum from expK partials (identical fixed-order computation in every block)
    float ks = 0.0f;
    for (int i = t; i < EXPK_BLOCKS; i += 512) ks += __ldcg(&g_Kpart[i]);
    ks = blockReduceSum(ks);
    const float invKs = 1.0f / ks;

    float Kr[ROWS_W][4], a[ROWS_W], prev[ROWS_W], b[4];
    bool rv[ROWS_W], cv[4];
    int cols[4];
    #pragma unroll
    for (int c = 0; c < 4; c++) {
        int j = lane + 32 * c;
        cols[c] = j; cv[c] = (j < WAY); b[c] = cv[c] ? 1.0f : 0.0f;
    }
    #pragma unroll
    for (int k = 0; k < ROWS_W; k++) {
        int r = rbase + k;
        rv[k] = (r < NU); a[k] = 1.0f; prev[k] = 0.0f;
        #pragma unroll
        for (int c = 0; c < 4; c++)
            Kr[k][c] = (rv[k] && cv[c]) ? g_Kmat[r * WAY + cols[c]] * invKs : 0.0f;
    }

    const uint32_t colBufAddr0 = (uint32_t)__cvta_generic_to_shared(&colsumBuf[0][0]);
    const uint32_t colBufAddr1 = (uint32_t)__cvta_generic_to_shared(&colsumBuf[1][0]);
    const uint32_t errAddr0    = (uint32_t)__cvta_generic_to_shared(&errBuf[0]);
    const uint32_t errAddr1    = (uint32_t)__cvta_generic_to_shared(&errBuf[1]);

    float rowsum[ROWS_W];
    for (int it = 0; it < 1000; ++it) {
        const int p = it & 1;
        float werr = 0.0f;
        {
            float anew[ROWS_W];
            #pragma unroll
            for (int k = 0; k < ROWS_W; k++) {
                float s = 0.0f;
                #pragma unroll
                for (int c = 0; c < 4; c++) s = fmaf(Kr[k][c], b[c], s);
                #pragma unroll
                for (int off = 16; off; off >>= 1) s += __shfl_xor_sync(0xffffffffu, s, off);
                rowsum[k] = a[k] * s;
                anew[k] = rv[k] ? a[k] / rowsum[k] : 0.0f;
                if (rv[k]) werr = fmaxf(werr, fabsf(prev[k] - rowsum[k]));
            }
            #pragma unroll
            for (int c = 0; c < 4; c++) {
                float s = 0.0f;
                #pragma unroll
                for (int k = 0; k < ROWS_W; k++) s = fmaf(Kr[k][c], anew[k], s);
                scolW[w][cols[c]] = cv[c] ? s : 0.0f;
            }
        }   // anew dead before the cluster barrier (register pressure)
        if (lane == 0) sWerr[w] = werr;
        __syncthreads();
        if (t < 128) {
            float s = scolW[0][t];
            #pragma unroll
            for (int ww = 1; ww < 16; ww++) s += scolW[ww][t];
            colsumBuf[p][t] = s;
        }
        if (t == 0) {
            float e = sWerr[0];
            #pragma unroll
            for (int ww = 1; ww < 16; ww++) e = fmaxf(e, sWerr[ww]);
            errBuf[p] = e;
        }
        CLUSTER_SYNC();
        if (t < 128) {
            uint32_t addr = (p ? colBufAddr1 : colBufAddr0) + t * 4;
            float s = 0.0f;
            #pragma unroll
            for (int bb = 0; bb < SKB; bb++) s += dsmem_ld(addr, (uint32_t)bb);
            sbcast[t] = s;
        }
        if (t == 0) {
            uint32_t addr = p ? errAddr1 : errAddr0;
            float e = 0.0f;
            #pragma unroll
            for (int bb = 0; bb < SKB; bb++) e = fmaxf(e, dsmem_ld(addr, (uint32_t)bb));
            sErrSh = e;
        }
        __syncthreads();
        if (sErrSh <= 1e-6f) break;     // a,b stay pre-update: exact reference semantics
        #pragma unroll
        for (int k = 0; k < ROWS_W; k++) {
            if (rv[k]) { a[k] = a[k] / rowsum[k]; prev[k] = rowsum[k]; }
        }
        #pragma unroll
        for (int c = 0; c < 4; c++) if (cv[c]) b[c] = 15.0f / sbcast[cols[c]];
        __syncthreads();                // protect sbcast before next overwrite
    }

    // epilogue: write Pu + per-block column-sum partials (for k_update's denom)
    float colacc[4] = {0.f, 0.f, 0.f, 0.f};
    #pragma unroll
    for (int k = 0; k < ROWS_W; k++) {
        if (!rv[k]) continue;
        int r = rbase + k;
        #pragma unroll
        for (int c = 0; c < 4; c++) {
            if (cv[c]) {
                float pval = a[k] * Kr[k][c] * b[c];
                g_Pu[r * WAY + cols[c]] = pval;
                colacc[c] += pval;
            }
        }
    }
    __syncthreads();
    #pragma unroll
    for (int c = 0; c < 4; c++) scolW[w][cols[c]] = cv[c] ? colacc[c] : 0.0f;
    __syncthreads();
    if (t < 128) {
        float s = scolW[0][t];
        #pragma unroll
        for (int ww = 1; ww < 16; ww++) s += scolW[ww][t];
        __stcg(&g_colPpart[blk * 128 + t], s);
    }
    CLUSTER_SYNC();                     // no CTA exits while peers may still read its smem
}

// ===== tensor-core epilogue GEMM: Epart[us][j,d] = sum_u Pu[u,j]*Zu[u,d]
__global__ void __launch_bounds__(256) k_epi() {
    const int n0 = blockIdx.x * 64;
    const int u0 = blockIdx.y * 375;
    const int t  = threadIdx.x;
    const int w  = t >> 5, lane = t & 31;
    const int gid = lane >> 2, tig = lane & 3;
    const int m0w = w * 16;

    __shared__ uint32_t As[16][132];
    __shared__ uint32_t Bs[16][68];

    float c[8][4];
    #pragma unroll
    for (int i = 0; i < 8; i++)
        #pragma unroll
        for (int jj = 0; jj < 4; jj++) c[i][jj] = 0.0f;

    const float* Zu = g_Z + (size_t)NL * D;

    for (int kt = 0; kt < 24; kt++) {
        #pragma unroll
        for (int p = 0; p < 8; p++) {
            int idx = t + 256 * p;
            int k = idx >> 7, m = idx & 127;
            int kg = kt * 16 + k;
            float v = (m < WAY && kg < 375) ? g_Pu[(u0 + kg) * WAY + m] : 0.0f;
            As[k][m] = f2tf32(v);
        }
        {
            int k = t >> 4, nn = (t & 15) * 4;
            int kg = kt * 16 + k;
            float4 v = make_float4(0.f, 0.f, 0.f, 0.f);
            if (kg < 375) v = *(const float4*)&Zu[(size_t)(u0 + kg) * D + n0 + nn];
            Bs[k][nn + 0] = f2tf32(v.x); Bs[k][nn + 1] = f2tf32(v.y);
            Bs[k][nn + 2] = f2tf32(v.z); Bs[k][nn + 3] = f2tf32(v.w);
        }
        __syncthreads();
        #pragma unroll
        for (int ks = 0; ks < 2; ks++) {
            const int kk = ks * 8;
            uint32_t a0 = As[kk + tig][m0w + gid];
            uint32_t a1 = As[kk + tig][m0w + gid + 8];
            uint32_t a2 = As[kk + tig + 4][m0w + gid];
            uint32_t a3 = As[kk + tig + 4][m0w + gid + 8];
            #pragma unroll
            for (int nt = 0; nt < 8; nt++) {
                uint32_t b0 = Bs[kk + tig][nt * 8 + gid];
                uint32_t b1 = Bs[kk + tig + 4][nt * 8 + gid];
                mma_tf32(c[nt], a0, a1, a2, a3, b0, b1);
            }
        }
        __syncthreads();
    }
    float* outp = g_Epart + (size_t)blockIdx.y * WAYD;
    #pragma unroll
    for (int nt = 0; nt < 8; nt++) {
        int dcol = n0 + nt * 8 + tig * 2;
        #pragma unroll
        for (int h = 0; h < 2; h++) {
            int j = m0w + gid + 8 * h;
            if (j < WAY) {
                outp[(size_t)j * D + dcol]     = c[nt][2 * h];
                outp[(size_t)j * D + dcol + 1] = c[nt][2 * h + 1];
            }
        }
    }
}

// one block per class: mus update + mn2 for next epoch
__global__ void __launch_bounds__(512) k_update() {
    const int j = blockIdx.x, t = threadIdx.x;
    __shared__ float sden;
    if (t == 0) {
        float s = 0.0f;
        #pragma unroll
        for (int bb = 0; bb < SKB; bb++) s += g_colPpart[bb * 128 + j];
        sden = 5.0f + s;
    }
    __syncthreads();
    const float invden = 1.0f / sden;
    float ss = 0.0f;
    #pragma unroll
    for (int q = 0; q < 8; q++) {
        int idx = j * D + t + 512 * q;
        float E = 0.0f;
        #pragma unroll
        for (int s = 0; s < 4; s++) E += g_Epart[s * WAYD + idx];
        float emus = (g_Sl[idx] + E) * invden;
        float m = g_mus[idx];
        m = m + ALPHAC * (emus - m);
        g_mus[idx] = m;
        ss += m * m;
    }
    ss = blockReduceSum(ss);
    if (t == 0) g_mn2[j] = ss;
}

// ---------------- output ----------------
__global__ void k_out(float* __restrict__ out) {
    int idx = blockIdx.x * blockDim.x + threadIdx.x;
    if (idx == 0) g_accN = 0;
    if (idx < NUW) out[idx] = logf(g_Pu[idx] + 1e-5f);
}

__global__ void k_acc(const int* __restrict__ labels) {
    int i = blockIdx.x * blockDim.x + threadIdx.x;
    if (i >= NU) return;
    const float* row = g_Pu + i * WAY;
    float best = row[0]; int bj = 0;
    for (int j = 1; j < WAY; j++) {
        float v = row[j];
        if (v > best) { best = v; bj = j; }
    }
    if (bj == labels[NL + i]) atomicAdd(&g_accN, 1);
}

__global__ void k_accw(float* __restrict__ out) {
    out[NUW] = (float)g_accN * (1.0f / NU);
}

// ---------------- launch ----------------
extern "C" void kernel_launch(void* const* d_in, const int* in_sizes, int n_in,
                              void* d_out, int out_size) {
    const float* X = (const float*)d_in[0];
    const int* labels = (const int*)d_in[1];
    float* out = (float*)d_out;

    k_pre1<<<NTOT, 256>>>(X);
    k_colmeans<<<D / 64, 256>>>();
    k_pre2<<<NTOT, 256>>>();
    k_Sl<<<WAY, 256>>>();

    for (int e = 0; e < 21; e++) {
        k_gram<<<dim3(24, 8), 256>>>();
        k_expK<<<EXPK_BLOCKS, 256>>>();
        k_sinkhorn<<<SKB, 512>>>();
        if (e < 20) {
            k_epi<<<dim3(64, 4), 256>>>();
            k_update<<<WAY, 512>>>();
        }
    }
    k_out<<<(NUW + 255) / 256, 256>>>(out);
    k_acc<<<(NU + 255) / 256, 256>>>(labels);
    if (out_size > NUW) k_accw<<<1, 1>>>(out);
}

// round 9
// speedup vs baseline: 2.7211x; 1.6982x over previous
#include <cuda_runtime.h>
#include <math.h>
#include <stdint.h>

// ---------------- problem constants ----------------
constexpr int D      = 4096;
constexpr int NTOT   = 2000;
constexpr int NL     = 500;
constexpr int NU     = 1500;
constexpr int WAY    = 100;
constexpr int NUW    = NU * WAY;      // 150000
constexpr int WAYD   = WAY * D;       // 409600
constexpr float LAMB   = 10.0f;
constexpr float ALPHAC = 0.2f;
constexpr int EXPK_BLOCKS = (NUW + 255) / 256;   // 586
constexpr int SKB = 8;                 // sinkhorn cluster blocks
constexpr int ROWS_W = 12;             // rows per warp (128 warps * 12 = 1536 >= 1500)

// ---------------- device scratch ----------------
__device__ float g_X1[NTOT * D];
__device__ float g_Z[NTOT * D];
__device__ float g_zn2[NTOT];
__device__ float g_meanL[D], g_meanU[D];
__device__ float g_Sl[WAYD];
__device__ float g_mus[WAYD];
__device__ float g_mn2[WAY];
__device__ float g_Cpart[8 * NUW];
__device__ float g_Kmat[NUW];
__device__ float g_Kpart[600];
__device__ float g_Pu[NUW];
__device__ float g_colPpart[SKB * 128];
__device__ float g_Epart[4 * WAYD];
__device__ int   g_accN;

// ---------------- helpers ----------------
__device__ __forceinline__ float blockReduceSum(float v) {
    static __shared__ float sh[32];
    __syncthreads();
    int lane = threadIdx.x & 31, wid = threadIdx.x >> 5;
    #pragma unroll
    for (int off = 16; off; off >>= 1) v += __shfl_xor_sync(0xffffffffu, v, off);
    if (lane == 0) sh[wid] = v;
    __syncthreads();
    int nw = (blockDim.x + 31) >> 5;
    float r = 0.0f;
    if (wid == 0) {
        r = (lane < nw) ? sh[lane] : 0.0f;
        #pragma unroll
        for (int off = 16; off; off >>= 1) r += __shfl_xor_sync(0xffffffffu, r, off);
        if (lane == 0) sh[0] = r;
    }
    __syncthreads();
    return sh[0];
}

// pack two floats into bf16x2 (lo in low half, hi in high half)
__device__ __forceinline__ uint32_t bfpack(float lo, float hi) {
    uint32_t r;
    asm("cvt.rn.bf16x2.f32 %0, %1, %2;" : "=r"(r) : "f"(hi), "f"(lo));
    return r;
}

__device__ __forceinline__ void mma_bf16(float c[4], uint32_t a0, uint32_t a1,
                                         uint32_t a2, uint32_t a3,
                                         uint32_t b0, uint32_t b1) {
    asm volatile(
        "mma.sync.aligned.m16n8k16.row.col.f32.bf16.bf16.f32 "
        "{%0,%1,%2,%3}, {%4,%5,%6,%7}, {%8,%9}, {%0,%1,%2,%3};\n"
        : "+f"(c[0]), "+f"(c[1]), "+f"(c[2]), "+f"(c[3])
        : "r"(a0), "r"(a1), "r"(a2), "r"(a3), "r"(b0), "r"(b1));
}

__device__ __forceinline__ float dsmem_ld(uint32_t local_addr, uint32_t rank) {
    float v;
    asm volatile(
        "{\n\t"
        ".reg .b32 ra;\n\t"
        "mapa.shared::cluster.u32 ra, %1, %2;\n\t"
        "ld.shared::cluster.f32 %0, [ra];\n\t"
        "}"
        : "=f"(v) : "r"(local_addr), "r"(rank));
    return v;
}

#define CLUSTER_SYNC() do { \
    asm volatile("barrier.cluster.arrive.aligned;" ::: "memory"); \
    asm volatile("barrier.cluster.wait.aligned;" ::: "memory"); \
} while (0)

// ---------------- preprocessing ----------------
__global__ void k_pre1(const float* __restrict__ X) {
    int row = blockIdx.x, t = threadIdx.x;
    __shared__ float buf[D];
    float ss = 0.0f;
    for (int d = t; d < D; d += blockDim.x) {
        float v = sqrtf(X[(size_t)row * D + d] + 1e-6f);
        buf[d] = v; ss += v * v;
    }
    ss = blockReduceSum(ss);
    float inv = 1.0f / fmaxf(sqrtf(ss), 1e-12f);
    for (int d = t; d < D; d += blockDim.x) g_X1[(size_t)row * D + d] = buf[d] * inv;
}

__global__ void k_colmeans() {
    int lane = threadIdx.x & 63;
    int part = threadIdx.x >> 6;         // 0..3
    int d = blockIdx.x * 64 + lane;
    __shared__ float sh[4][64];
    float sL = 0.0f;
    for (int i = part * 125; i < (part + 1) * 125; i++) sL += g_X1[(size_t)i * D + d];
    sh[part][lane] = sL;
    __syncthreads();
    if (part == 0)
        g_meanL[d] = (sh[0][lane] + sh[1][lane] + sh[2][lane] + sh[3][lane]) * (1.0f / NL);
    __syncthreads();
    float sU = 0.0f;
    for (int i = NL + part * 375; i < NL + (part + 1) * 375; i++) sU += g_X1[(size_t)i * D + d];
    sh[part][lane] = sU;
    __syncthreads();
    if (part == 0)
        g_meanU[d] = (sh[0][lane] + sh[1][lane] + sh[2][lane] + sh[3][lane]) * (1.0f / NU);
}

__global__ void k_pre2() {
    int row = blockIdx.x, t = threadIdx.x;
    __shared__ float buf[D];
    const float* mean = (row < NL) ? g_meanL : g_meanU;
    float ss = 0.0f;
    for (int d = t; d < D; d += blockDim.x) {
        float v = g_X1[(size_t)row * D + d] - mean[d];
        buf[d] = v; ss += v * v;
    }
    ss = blockReduceSum(ss);
    float inv = 1.0f / fmaxf(sqrtf(ss), 1e-12f);
    if (t == 0) g_zn2[row] = ss * inv * inv;
    for (int d = t; d < D; d += blockDim.x) g_Z[(size_t)row * D + d] = buf[d] * inv;
}

// one block per class: Sl, mus0, mn2
__global__ void k_Sl() {
    int c = blockIdx.x, t = threadIdx.x;
    float ss = 0.0f;
    #pragma unroll
    for (int q = 0; q < 16; q++) {
        int d = t + 256 * q;
        float s = 0.0f;
        #pragma unroll
        for (int k = 0; k < 5; k++) s += g_Z[(size_t)(k * WAY + c) * D + d];
        g_Sl[c * D + d] = s;
        float m = s * 0.2f;
        g_mus[c * D + d] = m;
        ss += m * m;
    }
    ss = blockReduceSum(ss);
    if (t == 0) g_mn2[c] = ss;
}

// ===== bf16 tensor-core gram: Cpart[ks][i,j] = sum over 512-k-chunk Zu[i,k]*mus[j,k]
// grid (24 m-blocks, 8 k-splits), 256 threads (8 warps), warp tile m16 x n56
__global__ void __launch_bounds__(256) k_gram() {
    const int r0 = blockIdx.x * 64;
    const int k0 = blockIdx.y * 512;
    const int t  = threadIdx.x;
    const int w  = t >> 5, lane = t & 31;
    const int gid = lane >> 2, tig = lane & 3;
    const int m0w = (w >> 1) * 16;
    const int n0w = (w & 1) * 56;

    __shared__ uint32_t As[64][36];   // [m][k-pair] bf16x2 (stride 36: conflict-free frag loads)
    __shared__ uint32_t Bs[112][36];  // [n][k-pair]

    float c[7][4];
    #pragma unroll
    for (int i = 0; i < 7; i++)
        #pragma unroll
        for (int jj = 0; jj < 4; jj++) c[i][jj] = 0.0f;

    const float* Zu = g_Z + (size_t)NL * D;
    const int arow = t >> 2;          // 0..63
    const int af4  = t & 3;

    for (int kt = 0; kt < 512; kt += 64) {
        const int kbase = k0 + kt;
        // A: 64 rows x 64 k (each thread 4 float4)
        #pragma unroll
        for (int i = 0; i < 4; i++) {
            int f4 = af4 + 4 * i;
            float4 v = make_float4(0.f, 0.f, 0.f, 0.f);
            if (r0 + arow < NU) v = *(const float4*)&Zu[(size_t)(r0 + arow) * D + kbase + f4 * 4];
            As[arow][f4 * 2]     = bfpack(v.x, v.y);
            As[arow][f4 * 2 + 1] = bfpack(v.z, v.w);
        }
        // B: 112 rows x 64 k (each thread 7 float4)
        #pragma unroll
        for (int i = 0; i < 7; i++) {
            int idx = t + 256 * i;
            int row = idx >> 4, f4 = idx & 15;
            float4 v = make_float4(0.f, 0.f, 0.f, 0.f);
            if (row < WAY) v = *(const float4*)&g_mus[(size_t)row * D + kbase + f4 * 4];
            Bs[row][f4 * 2]     = bfpack(v.x, v.y);
            Bs[row][f4 * 2 + 1] = bfpack(v.z, v.w);
        }
        __syncthreads();
        #pragma unroll
        for (int ks = 0; ks < 4; ks++) {
            const int kp = ks * 8;
            uint32_t a0 = As[m0w + gid][kp + tig];
            uint32_t a1 = As[m0w + gid + 8][kp + tig];
            uint32_t a2 = As[m0w + gid][kp + tig + 4];
            uint32_t a3 = As[m0w + gid + 8][kp + tig + 4];
            #pragma unroll
            for (int nt = 0; nt < 7; nt++) {
                uint32_t b0 = Bs[n0w + nt * 8 + gid][kp + tig];
                uint32_t b1 = Bs[n0w + nt * 8 + gid][kp + tig + 4];
                mma_bf16(c[nt], a0, a1, a2, a3, b0, b1);
            }
        }
        __syncthreads();
    }
    float* out = g_Cpart + (size_t)blockIdx.y * NUW;
    #pragma unroll
    for (int nt = 0; nt < 7; nt++) {
        int j0 = n0w + nt * 8 + tig * 2;
        int gr0 = r0 + m0w + gid;
        #pragma unroll
        for (int h = 0; h < 2; h++) {
            int gr = gr0 + 8 * h;
            if (gr < NU) {
                if (j0 < WAY)     out[gr * WAY + j0]     = c[nt][2 * h];
                if (j0 + 1 < WAY) out[gr * WAY + j0 + 1] = c[nt][2 * h + 1];
            }
        }
    }
}

// K = exp(-lam*dist); block partial sums
__global__ void k_expK() {
    int idx = blockIdx.x * blockDim.x + threadIdx.x;
    float kv = 0.0f;
    if (idx < NUW) {
        int i = idx / WAY, j = idx - i * WAY;
        float c = 0.0f;
        #pragma unroll
        for (int s = 0; s < 8; s++) c += g_Cpart[s * NUW + idx];
        float d2 = g_zn2[NL + i] + g_mn2[j] - 2.0f * c;
        float dist = sqrtf(fmaxf(d2, 1e-12f));
        kv = expf(-LAMB * dist);
        g_Kmat[idx] = kv;
    }
    float bs = blockReduceSum(kv);
    if (threadIdx.x == 0) g_Kpart[blockIdx.x] = bs;
}

// ---------------- cluster-based persistent sinkhorn (8 CTAs x 512) ----------------
__global__ void __cluster_dims__(SKB, 1, 1) __launch_bounds__(512, 1) k_sinkhorn() {
    const int t = threadIdx.x, w = t >> 5, lane = t & 31;
    const int blk = blockIdx.x;           // == cluster rank (single cluster)
    const int gw  = blk * 16 + w;         // global warp 0..127
    const int rbase = gw * ROWS_W;
    __shared__ float scolW[16][128];
    __shared__ float sWerr[16];
    __shared__ float colsumBuf[2][128];
    __shared__ float errBuf[2];
    __shared__ float sbcast[128];
    __shared__ float sErrSh;

    // Ksum from expK partials (identical fixed-order computation in every block)
    float ks = 0.0f;
    for (int i = t; i < EXPK_BLOCKS; i += 512) ks += __ldcg(&g_Kpart[i]);
    ks = blockReduceSum(ks);
    const float invKs = 1.0f / ks;

    float Kr[ROWS_W][4], a[ROWS_W], prev[ROWS_W], b[4];
    bool rv[ROWS_W], cv[4];
    int cols[4];
    #pragma unroll
    for (int c = 0; c < 4; c++) {
        int j = lane + 32 * c;
        cols[c] = j; cv[c] = (j < WAY); b[c] = cv[c] ? 1.0f : 0.0f;
    }
    #pragma unroll
    for (int k = 0; k < ROWS_W; k++) {
        int r = rbase + k;
        rv[k] = (r < NU); a[k] = 1.0f; prev[k] = 0.0f;
        #pragma unroll
        for (int c = 0; c < 4; c++)
            Kr[k][c] = (rv[k] && cv[c]) ? g_Kmat[r * WAY + cols[c]] * invKs : 0.0f;
    }

    const uint32_t colBufAddr0 = (uint32_t)__cvta_generic_to_shared(&colsumBuf[0][0]);
    const uint32_t colBufAddr1 = (uint32_t)__cvta_generic_to_shared(&colsumBuf[1][0]);
    const uint32_t errAddr0    = (uint32_t)__cvta_generic_to_shared(&errBuf[0]);
    const uint32_t errAddr1    = (uint32_t)__cvta_generic_to_shared(&errBuf[1]);

    float rowsum[ROWS_W];
    for (int it = 0; it < 1000; ++it) {
        const int p = it & 1;
        float werr = 0.0f;
        {
            float anew[ROWS_W];
            #pragma unroll
            for (int k = 0; k < ROWS_W; k++) {
                float s = 0.0f;
                #pragma unroll
                for (int c = 0; c < 4; c++) s = fmaf(Kr[k][c], b[c], s);
                #pragma unroll
                for (int off = 16; off; off >>= 1) s += __shfl_xor_sync(0xffffffffu, s, off);
                rowsum[k] = a[k] * s;
                anew[k] = rv[k] ? a[k] / rowsum[k] : 0.0f;
                if (rv[k]) werr = fmaxf(werr, fabsf(prev[k] - rowsum[k]));
            }
            #pragma unroll
            for (int c = 0; c < 4; c++) {
                float s = 0.0f;
                #pragma unroll
                for (int k = 0; k < ROWS_W; k++) s = fmaf(Kr[k][c], anew[k], s);
                scolW[w][cols[c]] = cv[c] ? s : 0.0f;
            }
        }   // anew dead before the cluster barrier (register pressure)
        if (lane == 0) sWerr[w] = werr;
        __syncthreads();
        if (t < 128) {
            float s = scolW[0][t];
            #pragma unroll
            for (int ww = 1; ww < 16; ww++) s += scolW[ww][t];
            colsumBuf[p][t] = s;
        }
        if (t == 0) {
            float e = sWerr[0];
            #pragma unroll
            for (int ww = 1; ww < 16; ww++) e = fmaxf(e, sWerr[ww]);
            errBuf[p] = e;
        }
        CLUSTER_SYNC();
        if (t < 128) {
            uint32_t addr = (p ? colBufAddr1 : colBufAddr0) + t * 4;
            float s = 0.0f;
            #pragma unroll
            for (int bb = 0; bb < SKB; bb++) s += dsmem_ld(addr, (uint32_t)bb);
            sbcast[t] = s;
        }
        if (t == 0) {
            uint32_t addr = p ? errAddr1 : errAddr0;
            float e = 0.0f;
            #pragma unroll
            for (int bb = 0; bb < SKB; bb++) e = fmaxf(e, dsmem_ld(addr, (uint32_t)bb));
            sErrSh = e;
        }
        __syncthreads();
        if (sErrSh <= 1e-6f) break;     // a,b stay pre-update: exact reference semantics
        #pragma unroll
        for (int k = 0; k < ROWS_W; k++) {
            if (rv[k]) { a[k] = a[k] / rowsum[k]; prev[k] = rowsum[k]; }
        }
        #pragma unroll
        for (int c = 0; c < 4; c++) if (cv[c]) b[c] = 15.0f / sbcast[cols[c]];
        __syncthreads();                // protect sbcast before next overwrite
    }

    // epilogue: write Pu + per-block column-sum partials (for k_update's denom)
    float colacc[4] = {0.f, 0.f, 0.f, 0.f};
    #pragma unroll
    for (int k = 0; k < ROWS_W; k++) {
        if (!rv[k]) continue;
        int r = rbase + k;
        #pragma unroll
        for (int c = 0; c < 4; c++) {
            if (cv[c]) {
                float pval = a[k] * Kr[k][c] * b[c];
                g_Pu[r * WAY + cols[c]] = pval;
                colacc[c] += pval;
            }
        }
    }
    __syncthreads();
    #pragma unroll
    for (int c = 0; c < 4; c++) scolW[w][cols[c]] = cv[c] ? colacc[c] : 0.0f;
    __syncthreads();
    if (t < 128) {
        float s = scolW[0][t];
        #pragma unroll
        for (int ww = 1; ww < 16; ww++) s += scolW[ww][t];
        __stcg(&g_colPpart[blk * 128 + t], s);
    }
    CLUSTER_SYNC();                     // no CTA exits while peers may still read its smem
}

// ===== bf16 tensor-core epilogue GEMM: Epart[us][j,d] = sum_u Pu[u,j]*Zu[u,d]
// grid (64 n-blocks, 4 u-splits), 256 threads (8 warps); 32-u tiles (12 per split)
__global__ void __launch_bounds__(256) k_epi() {
    const int n0 = blockIdx.x * 64;
    const int u0 = blockIdx.y * 375;
    const int t  = threadIdx.x;
    const int w  = t >> 5, lane = t & 31;
    const int gid = lane >> 2, tig = lane & 3;
    const int m0w = w * 16;

    __shared__ uint32_t As[128][20];  // [class][u-pair] bf16x2 (stride 20: conflict-free)
    __shared__ uint32_t Bs[64][20];   // [dim][u-pair]

    float c[8][4];
    #pragma unroll
    for (int i = 0; i < 8; i++)
        #pragma unroll
        for (int jj = 0; jj < 4; jj++) c[i][jj] = 0.0f;

    const float* Zu = g_Z + (size_t)NL * D;
    const int am  = t & 127;          // class for A loads
    const int ah  = t >> 7;           // 0..1
    const int bup = t >> 4;           // u-pair 0..15 for B loads
    const int bnn = (t & 15) * 4;     // dim group

    for (int kt = 0; kt < 12; kt++) {
        const int ub = kt * 32;
        // A: Pu^T pack -> As[class][u-pair]
        #pragma unroll
        for (int i = 0; i < 8; i++) {
            int kp = ah * 8 + i;
            int u = ub + kp * 2;
            float lo = (am < WAY && u     < 375) ? g_Pu[(u0 + u) * WAY + am]     : 0.0f;
            float hi = (am < WAY && u + 1 < 375) ? g_Pu[(u0 + u + 1) * WAY + am] : 0.0f;
            As[am][kp] = bfpack(lo, hi);
        }
        // B: Zu pack -> Bs[dim][u-pair]
        {
            int u = ub + bup * 2;
            float4 v0 = make_float4(0.f, 0.f, 0.f, 0.f);
            float4 v1 = make_float4(0.f, 0.f, 0.f, 0.f);
            if (u     < 375) v0 = *(const float4*)&Zu[(size_t)(u0 + u) * D + n0 + bnn];
            if (u + 1 < 375) v1 = *(const float4*)&Zu[(size_t)(u0 + u + 1) * D + n0 + bnn];
            Bs[bnn + 0][bup] = bfpack(v0.x, v1.x);
            Bs[bnn + 1][bup] = bfpack(v0.y, v1.y);
            Bs[bnn + 2][bup] = bfpack(v0.z, v1.z);
            Bs[bnn + 3][bup] = bfpack(v0.w, v1.w);
        }
        __syncthreads();
        #pragma unroll
        for (int ks = 0; ks < 2; ks++) {
            const int kp = ks * 8;
            uint32_t a0 = As[m0w + gid][kp + tig];
            uint32_t a1 = As[m0w + gid + 8][kp + tig];
            uint32_t a2 = As[m0w + gid][kp + tig + 4];
            uint32_t a3 = As[m0w + gid + 8][kp + tig + 4];
            #pragma unroll
            for (int nt = 0; nt < 8; nt++) {
                uint32_t b0 = Bs[nt * 8 + gid][kp + tig];
                uint32_t b1 = Bs[nt * 8 + gid][kp + tig + 4];
                mma_bf16(c[nt], a0, a1, a2, a3, b0, b1);
            }
        }
        __syncthreads();
    }
    float* outp = g_Epart + (size_t)blockIdx.y * WAYD;
    #pragma unroll
    for (int nt = 0; nt < 8; nt++) {
        int dcol = n0 + nt * 8 + tig * 2;
        #pragma unroll
        for (int h = 0; h < 2; h++) {
            int j = m0w + gid + 8 * h;
            if (j < WAY) {
                outp[(size_t)j * D + dcol]     = c[nt][2 * h];
                outp[(size_t)j * D + dcol + 1] = c[nt][2 * h + 1];
            }
        }
    }
}

// one block per class: mus update + mn2 for next epoch
__global__ void __launch_bounds__(512) k_update() {
    const int j = blockIdx.x, t = threadIdx.x;
    __shared__ float sden;
    if (t == 0) {
        float s = 0.0f;
        #pragma unroll
        for (int bb = 0; bb < SKB; bb++) s += g_colPpart[bb * 128 + j];
        sden = 5.0f + s;
    }
    __syncthreads();
    const float invden = 1.0f / sden;
    float ss = 0.0f;
    #pragma unroll
    for (int q = 0; q < 8; q++) {
        int idx = j * D + t + 512 * q;
        float E = 0.0f;
        #pragma unroll
        for (int s = 0; s < 4; s++) E += g_Epart[s * WAYD + idx];
        float emus = (g_Sl[idx] + E) * invden;
        float m = g_mus[idx];
        m = m + ALPHAC * (emus - m);
        g_mus[idx] = m;
        ss += m * m;
    }
    ss = blockReduceSum(ss);
    if (t == 0) g_mn2[j] = ss;
}

// ---------------- output ----------------
__global__ void k_out(float* __restrict__ out) {
    int idx = blockIdx.x * blockDim.x + threadIdx.x;
    if (idx == 0) g_accN = 0;
    if (idx < NUW) out[idx] = logf(g_Pu[idx] + 1e-5f);
}

__global__ void k_acc(const int* __restrict__ labels) {
    int i = blockIdx.x * blockDim.x + threadIdx.x;
    if (i >= NU) return;
    const float* row = g_Pu + i * WAY;
    float best = row[0]; int bj = 0;
    for (int j = 1; j < WAY; j++) {
        float v = row[j];
        if (v > best) { best = v; bj = j; }
    }
    if (bj == labels[NL + i]) atomicAdd(&g_accN, 1);
}

__global__ void k_accw(float* __restrict__ out) {
    out[NUW] = (float)g_accN * (1.0f / NU);
}

// ---------------- launch ----------------
extern "C" void kernel_launch(void* const* d_in, const int* in_sizes, int n_in,
                              void* d_out, int out_size) {
    const float* X = (const float*)d_in[0];
    const int* labels = (const int*)d_in[1];
    float* out = (float*)d_out;

    k_pre1<<<NTOT, 256>>>(X);
    k_colmeans<<<D / 64, 256>>>();
    k_pre2<<<NTOT, 256>>>();
    k_Sl<<<WAY, 256>>>();

    for (int e = 0; e < 21; e++) {
        k_gram<<<dim3(24, 8), 256>>>();
        k_expK<<<EXPK_BLOCKS, 256>>>();
        k_sinkhorn<<<SKB, 512>>>();
        if (e < 20) {
            k_epi<<<dim3(64, 4), 256>>>();
            k_update<<<WAY, 512>>>();
        }
    }
    k_out<<<(NUW + 255) / 256, 256>>>(out);
    k_acc<<<(NU + 255) / 256, 256>>>(labels);
    if (out_size > NUW) k_accw<<<1, 1>>>(out);
}